// round 14
// baseline (speedup 1.0000x reference)
#include <cuda_runtime.h>
#include <cuda_bf16.h>
#include <cuda_fp16.h>
#include <math.h>

#define NN 100000
#define EE 1600000
#define HID 128
#define BN_EPS 1e-5f
#define NB_SCAN 391   // ceil(NN/256)

typedef unsigned long long ull;
typedef unsigned int u32;

// ---------------- scratch (no allocations allowed) ----------------
__device__ float g_bufA[(size_t)NN * HID];   // fp16 P lives here
__device__ float g_bufB[(size_t)NN * HID];   // fp16 H lives here
__device__ int   g_deg[NN];                  // zeroed at END of each run (and at load)
__device__ int   g_off[NN];
__device__ int   g_cur[NN];
__device__ float g_dinv[NN];
__device__ int   g_csr[EE];
__device__ volatile ull g_blk[512];          // scan aggregates: (flag<<32)|sum, zeroed at end of run
__device__ int   g_is64;
__device__ char  g_wplanes[4 * 65536];       // 4 W matrices x (hi 32KB + lo 32KB)

// ---------------- helpers ----------------
__device__ __forceinline__ u32 smem_u32(const void* p) {
    u32 a;
    asm("{ .reg .u64 t; cvta.to.shared.u64 t, %1; cvt.u32.u64 %0, t; }" : "=r"(a) : "l"(p));
    return a;
}

__device__ __forceinline__ void ldsm4(u32 addr, u32* r) {
    asm volatile("ldmatrix.sync.aligned.m8n8.x4.shared.b16 {%0,%1,%2,%3}, [%4];"
        : "=r"(r[0]), "=r"(r[1]), "=r"(r[2]), "=r"(r[3]) : "r"(addr));
}

__device__ __forceinline__ void mma_bf16(float* c, const u32* a, u32 b0, u32 b1) {
    asm volatile("mma.sync.aligned.m16n8k16.row.col.f32.bf16.bf16.f32 "
        "{%0,%1,%2,%3}, {%4,%5,%6,%7}, {%8,%9}, {%0,%1,%2,%3};"
        : "+f"(c[0]), "+f"(c[1]), "+f"(c[2]), "+f"(c[3])
        : "r"(a[0]), "r"(a[1]), "r"(a[2]), "r"(a[3]), "r"(b0), "r"(b1));
}

__device__ __forceinline__ void split8(const float* f, uint4& hi, uint4& lo) {
    unsigned short h[8], l[8];
#pragma unroll
    for (int j = 0; j < 8; j++) {
        __nv_bfloat16 bh = __float2bfloat16(f[j]);
        float fh = __bfloat162float(bh);
        __nv_bfloat16 bl = __float2bfloat16(f[j] - fh);
        h[j] = __bfloat16_as_ushort(bh);
        l[j] = __bfloat16_as_ushort(bl);
    }
    hi.x = (u32)h[0] | ((u32)h[1] << 16); hi.y = (u32)h[2] | ((u32)h[3] << 16);
    hi.z = (u32)h[4] | ((u32)h[5] << 16); hi.w = (u32)h[6] | ((u32)h[7] << 16);
    lo.x = (u32)l[0] | ((u32)l[1] << 16); lo.y = (u32)l[2] | ((u32)l[3] << 16);
    lo.z = (u32)l[4] | ((u32)l[5] << 16); lo.w = (u32)l[6] | ((u32)l[7] << 16);
}

__device__ __forceinline__ u32 pack_hilo2(float x0, float x1, u32& lo) {
    __nv_bfloat16 h0 = __float2bfloat16(x0);
    __nv_bfloat16 l0 = __float2bfloat16(x0 - __bfloat162float(h0));
    __nv_bfloat16 h1 = __float2bfloat16(x1);
    __nv_bfloat16 l1 = __float2bfloat16(x1 - __bfloat162float(h1));
    lo = (u32)__bfloat16_as_ushort(l0) | ((u32)__bfloat16_as_ushort(l1) << 16);
    return (u32)__bfloat16_as_ushort(h0) | ((u32)__bfloat16_as_ushort(h1) << 16);
}

__device__ __forceinline__ int edge_at(const void* ei, long long i, int is64) {
    if (is64) return (int)((const long long*)ei)[i];
    return ((const int*)ei)[i];
}

// fp16 row fragment load (4 cols = 8 bytes)
__device__ __forceinline__ float4 ldrow_h(const __half* __restrict__ P, size_t row, int j0) {
    uint2 r = *(const uint2*)(P + row * 128 + j0);
    __half2 h0 = *reinterpret_cast<__half2*>(&r.x);
    __half2 h1 = *reinterpret_cast<__half2*>(&r.y);
    float2 f0 = __half22float2(h0), f1 = __half22float2(h1);
    return make_float4(f0.x, f0.y, f1.x, f1.y);
}

// ---------------- merged mainloop: warp tile 32x32, split-bf16 (3 products) ----------------
__device__ __forceinline__ void run_mainloop_m(u32 AHIb, u32 ALOb, u32 BHIb, u32 BLOb,
                                               int m0, int n0, int l, float acc[2][4][4]) {
    int quad = l >> 3;
    int aRow0 = m0 + (l & 7) + ((quad & 1) << 3);
    int aKsel = (quad >> 1) << 4;
    u32 axor = (u32)((aRow0 & 7) << 4);
    u32 arb0 = (u32)(aRow0 * 256);
    u32 arb1 = (u32)((aRow0 + 16) * 256);

    int bRow0 = n0 + (l & 7) + ((quad >> 1) << 3);
    int bKsel = (quad & 1) << 4;
    u32 bxor = (u32)((bRow0 & 7) << 4);
    u32 brb0 = (u32)(bRow0 * 256);
    u32 brb1 = (u32)((bRow0 + 16) * 256);

#pragma unroll
    for (int mf = 0; mf < 2; mf++)
#pragma unroll
        for (int j = 0; j < 4; j++)
#pragma unroll
            for (int k = 0; k < 4; k++) acc[mf][j][k] = 0.f;

#pragma unroll
    for (int ks = 0; ks < 8; ks++) {
        u32 kbA = (u32)(ks * 32 + aKsel) ^ axor;
        u32 kbB = (u32)(ks * 32 + bKsel) ^ bxor;
        u32 ah0[4], ah1[4], al0[4], al1[4];
        ldsm4(AHIb + arb0 + kbA, ah0);
        ldsm4(AHIb + arb1 + kbA, ah1);
        ldsm4(ALOb + arb0 + kbA, al0);
        ldsm4(ALOb + arb1 + kbA, al1);
        u32 bh[2][4], bl[2][4];
        ldsm4(BHIb + brb0 + kbB, bh[0]);
        ldsm4(BHIb + brb1 + kbB, bh[1]);
        ldsm4(BLOb + brb0 + kbB, bl[0]);
        ldsm4(BLOb + brb1 + kbB, bl[1]);
#pragma unroll
        for (int j = 0; j < 4; j++) {
            u32 h0 = bh[j >> 1][(j & 1) * 2], h1 = bh[j >> 1][(j & 1) * 2 + 1];
            u32 l0 = bl[j >> 1][(j & 1) * 2], l1 = bl[j >> 1][(j & 1) * 2 + 1];
            mma_bf16(acc[0][j], ah0, h0, h1);
            mma_bf16(acc[1][j], ah1, h0, h1);
            mma_bf16(acc[0][j], ah0, l0, l1);
            mma_bf16(acc[1][j], ah1, l0, l1);
            mma_bf16(acc[0][j], al0, h0, h1);
            mma_bf16(acc[1][j], al1, h0, h1);
        }
    }
}

// fill A planes: 64 rows, 256 threads, fp32 source
__device__ __forceinline__ void fill_A64(char* smem, int OFF_HI, int OFF_LO,
                                         const float* __restrict__ A, int r0, int t) {
#pragma unroll
    for (int i = 0; i < 4; i++) {
        int q = i * 256 + t;
        int r = q >> 4;
        int c = q & 15;
        int gr = r0 + r;
        uint4 hi, lo;
        if (gr < NN) {
            float f[8];
            float4 a0 = *(const float4*)(A + (size_t)gr * 128 + c * 8);
            float4 a1 = *(const float4*)(A + (size_t)gr * 128 + c * 8 + 4);
            f[0] = a0.x; f[1] = a0.y; f[2] = a0.z; f[3] = a0.w;
            f[4] = a1.x; f[5] = a1.y; f[6] = a1.z; f[7] = a1.w;
            split8(f, hi, lo);
        } else {
            hi = make_uint4(0, 0, 0, 0);
            lo = make_uint4(0, 0, 0, 0);
        }
        u32 off = r * 256 + ((c * 16) ^ ((r & 7) << 4));
        *(uint4*)(smem + OFF_HI + off) = hi;
        *(uint4*)(smem + OFF_LO + off) = lo;
    }
}

// fill A planes: 64 rows, 256 threads, fp16 source
__device__ __forceinline__ void fill_A64h(char* smem, int OFF_HI, int OFF_LO,
                                          const __half* __restrict__ A, int r0, int t) {
#pragma unroll
    for (int i = 0; i < 4; i++) {
        int q = i * 256 + t;
        int r = q >> 4;
        int c = q & 15;
        int gr = r0 + r;
        uint4 hi, lo;
        if (gr < NN) {
            uint4 raw = *(const uint4*)(A + (size_t)gr * 128 + c * 8);  // 8 halfs = 16B
            __half2* hp = (__half2*)&raw;
            float f[8];
#pragma unroll
            for (int j = 0; j < 4; j++) {
                float2 fv = __half22float2(hp[j]);
                f[2 * j] = fv.x;
                f[2 * j + 1] = fv.y;
            }
            split8(f, hi, lo);
        } else {
            hi = make_uint4(0, 0, 0, 0);
            lo = make_uint4(0, 0, 0, 0);
        }
        u32 off = r * 256 + ((c * 16) ^ ((r & 7) << 4));
        *(uint4*)(smem + OFF_HI + off) = hi;
        *(uint4*)(smem + OFF_LO + off) = lo;
    }
}

// copy precomputed W planes (64 KB) into smem with 256 threads
__device__ __forceinline__ void copy_B256(char* smem, int OFF_HI, int OFF_LO,
                                          int widx, int t) {
    const uint4* src = (const uint4*)(g_wplanes + widx * 65536);
#pragma unroll
    for (int i = 0; i < 8; i++) {
        int idx = i * 256 + t;
        ((uint4*)(smem + OFF_HI))[idx] = src[idx];
        ((uint4*)(smem + OFF_LO))[idx] = src[2048 + idx];
    }
}

// ---------------- stream 2: W planes only (4 blocks) ----------------
__global__ void wplanes_kernel(const float* __restrict__ W1, const float* __restrict__ W2,
                               const float* __restrict__ Wf1, const float* __restrict__ Wf2) {
    const float* W = (blockIdx.x == 0) ? W1 : (blockIdx.x == 1) ? W2 :
                     (blockIdx.x == 2) ? Wf1 : Wf2;
    char* dst = g_wplanes + blockIdx.x * 65536;
    int t = threadIdx.x;
#pragma unroll
    for (int i = 0; i < 8; i++) {
        int q = i * 256 + t;
        int n = q & 127;
        int kb = q >> 7;
        float f[8];
#pragma unroll
        for (int j = 0; j < 8; j++) f[j] = W[(kb * 8 + j) * 128 + n];
        uint4 hi, lo;
        split8(f, hi, lo);
        u32 off = n * 256 + ((kb * 16) ^ ((n & 7) << 4));
        *(uint4*)(dst + off) = hi;
        *(uint4*)(dst + 32768 + off) = lo;
    }
}

// ---------------- dtype detect + degree histogram (8-wide grid-stride) ----------------
// Requires g_deg == 0 on entry (zeroed at load and at END of each run by mlp).
__global__ void degdet_kernel(const void* __restrict__ ei) {
    int b = blockIdx.x, t = threadIdx.x;
    __shared__ int nz;
    if (t == 0) nz = 0;
    __syncthreads();
    const int* ei32 = (const int*)ei;
    int bad = 0;
    for (int j = t; j < 2048; j += 256)
        if (ei32[2 * j + 1] != 0) bad = 1;
    if (bad) atomicOr(&nz, 1);
    __syncthreads();
    int is64 = (nz == 0) ? 1 : 0;
    if (b == 0 && t == 0) g_is64 = is64;

    const long long S = (long long)NB_SCAN * 256;
    long long e = (long long)b * 256 + t;
    for (; e + 7 * S < EE; e += 8 * S) {
        int d[8];
#pragma unroll
        for (int u = 0; u < 8; u++) d[u] = edge_at(ei, EE + e + u * S, is64);
#pragma unroll
        for (int u = 0; u < 8; u++) atomicAdd(&g_deg[d[u]], 1);
    }
    for (; e < EE; e += S) {
        int d = edge_at(ei, EE + e, is64);
        atomicAdd(&g_deg[d], 1);
    }
}

// ---------------- single-pass scan: block aggregates + windowed lookback sum ----------------
// Requires g_blk == 0 on entry (zeroed at load and at END of each run by mlp).
__global__ void scan_lb_kernel() {
    __shared__ int sm[256];
    __shared__ int s_prefix;
    int b = blockIdx.x, t = threadIdx.x;
    int i = b * 256 + t;
    int d = (i < NN) ? g_deg[i] : 0;
    sm[t] = d;
    __syncthreads();
    for (int s = 1; s < 256; s <<= 1) {
        int add = (t >= s) ? sm[t - s] : 0;
        __syncthreads();
        sm[t] += add;
        __syncthreads();
    }
    // publish this block's aggregate (single 8B store: flag in high word)
    if (t == 255) {
        ull v = (1ull << 32) | (u32)sm[255];
        g_blk[b] = v;
    }
    // warp 0: sum aggregates of all predecessor blocks (windowed, spin on flags)
    if (t < 32) {
        int prefix = 0;
        for (int base = 0; base < b; base += 32) {
            int idx = base + t;
            int val = 0;
            if (idx < b) {
                ull v;
                do { v = g_blk[idx]; } while ((v >> 32) == 0);
                val = (int)(u32)v;
            }
#pragma unroll
            for (int o = 16; o; o >>= 1) val += __shfl_down_sync(0xFFFFFFFFu, val, o);
            if (t == 0) prefix += val;
        }
        if (t == 0) s_prefix = prefix;
    }
    __syncthreads();
    if (i < NN) {
        int excl = s_prefix + sm[t] - d;
        g_off[i] = excl;
        g_cur[i] = excl;
        g_dinv[i] = rsqrtf((float)(d + 1));
    }
}

// ---------------- CSR fill (8 edges per thread) ----------------
__global__ void fill_kernel(const void* __restrict__ ei) {
    long long base = (long long)(blockIdx.x * blockDim.x + threadIdx.x) * 8;
    int is64 = g_is64;
    int s[8], d[8];
#pragma unroll
    for (int u = 0; u < 8; u++) {
        if (base + u < EE) {
            s[u] = edge_at(ei, base + u, is64);
            d[u] = edge_at(ei, (long long)EE + base + u, is64);
        } else {
            s[u] = -1;
        }
    }
#pragma unroll
    for (int u = 0; u < 8; u++) {
        if (s[u] >= 0) {
            int pos = atomicAdd(&g_cur[d[u]], 1);
            g_csr[pos] = s[u];
        }
    }
}

// ---------------- aggregation: gather fp16 P -> fp32 accum -> fp16 out ----------------
__global__ void agg_kernel(const __half* __restrict__ P, __half* __restrict__ O,
                           const float* __restrict__ bias,
                           const float* __restrict__ g, const float* __restrict__ be,
                           const float* __restrict__ m, const float* __restrict__ v) {
    int node = (blockIdx.x * blockDim.x + threadIdx.x) >> 5;
    int lane = threadIdx.x & 31;
    if (node >= NN) return;
    float dn = g_dinv[node];
    int j0 = lane * 4;

    float4 self = ldrow_h(P, (size_t)node, j0);
    float4 acc;
    acc.x = self.x * dn;
    acc.y = self.y * dn;
    acc.z = self.z * dn;
    acc.w = self.w * dn;

    int st = g_off[node];
    int en = st + g_deg[node];
    int e = st;
    for (; e + 8 <= en; e += 8) {
        int s0 = g_csr[e],     s1 = g_csr[e + 1], s2 = g_csr[e + 2], s3 = g_csr[e + 3];
        int s4 = g_csr[e + 4], s5 = g_csr[e + 5], s6 = g_csr[e + 6], s7 = g_csr[e + 7];
        float w0 = g_dinv[s0], w1 = g_dinv[s1], w2 = g_dinv[s2], w3 = g_dinv[s3];
        float w4 = g_dinv[s4], w5 = g_dinv[s5], w6 = g_dinv[s6], w7 = g_dinv[s7];
        float4 p0 = ldrow_h(P, (size_t)s0, j0);
        float4 p1 = ldrow_h(P, (size_t)s1, j0);
        float4 p2 = ldrow_h(P, (size_t)s2, j0);
        float4 p3 = ldrow_h(P, (size_t)s3, j0);
        float4 p4 = ldrow_h(P, (size_t)s4, j0);
        float4 p5 = ldrow_h(P, (size_t)s5, j0);
        float4 p6 = ldrow_h(P, (size_t)s6, j0);
        float4 p7 = ldrow_h(P, (size_t)s7, j0);
        acc.x += p0.x * w0 + p1.x * w1 + p2.x * w2 + p3.x * w3 +
                 p4.x * w4 + p5.x * w5 + p6.x * w6 + p7.x * w7;
        acc.y += p0.y * w0 + p1.y * w1 + p2.y * w2 + p3.y * w3 +
                 p4.y * w4 + p5.y * w5 + p6.y * w6 + p7.y * w7;
        acc.z += p0.z * w0 + p1.z * w1 + p2.z * w2 + p3.z * w3 +
                 p4.z * w4 + p5.z * w5 + p6.z * w6 + p7.z * w7;
        acc.w += p0.w * w0 + p1.w * w1 + p2.w * w2 + p3.w * w3 +
                 p4.w * w4 + p5.w * w5 + p6.w * w6 + p7.w * w7;
    }
    for (; e + 4 <= en; e += 4) {
        int s0 = g_csr[e], s1 = g_csr[e + 1], s2 = g_csr[e + 2], s3 = g_csr[e + 3];
        float w0 = g_dinv[s0], w1 = g_dinv[s1], w2 = g_dinv[s2], w3 = g_dinv[s3];
        float4 p0 = ldrow_h(P, (size_t)s0, j0);
        float4 p1 = ldrow_h(P, (size_t)s1, j0);
        float4 p2 = ldrow_h(P, (size_t)s2, j0);
        float4 p3 = ldrow_h(P, (size_t)s3, j0);
        acc.x += p0.x * w0 + p1.x * w1 + p2.x * w2 + p3.x * w3;
        acc.y += p0.y * w0 + p1.y * w1 + p2.y * w2 + p3.y * w3;
        acc.z += p0.z * w0 + p1.z * w1 + p2.z * w2 + p3.z * w3;
        acc.w += p0.w * w0 + p1.w * w1 + p2.w * w2 + p3.w * w3;
    }
    for (; e < en; e++) {
        int s = g_csr[e];
        float w = g_dinv[s];
        float4 p = ldrow_h(P, (size_t)s, j0);
        acc.x += p.x * w;
        acc.y += p.y * w;
        acc.z += p.z * w;
        acc.w += p.w * w;
    }

    float4 b4  = *(const float4*)(bias + j0);
    float4 g4  = *(const float4*)(g + j0);
    float4 be4 = *(const float4*)(be + j0);
    float4 m4  = *(const float4*)(m + j0);
    float4 v4  = *(const float4*)(v + j0);

    float4 o;
    { float x = acc.x * dn + b4.x; float s = g4.x * rsqrtf(v4.x + BN_EPS); o.x = fmaxf((x - m4.x) * s + be4.x, 0.f); }
    { float x = acc.y * dn + b4.y; float s = g4.y * rsqrtf(v4.y + BN_EPS); o.y = fmaxf((x - m4.y) * s + be4.y, 0.f); }
    { float x = acc.z * dn + b4.z; float s = g4.z * rsqrtf(v4.z + BN_EPS); o.z = fmaxf((x - m4.z) * s + be4.z, 0.f); }
    { float x = acc.w * dn + b4.w; float s = g4.w * rsqrtf(v4.w + BN_EPS); o.w = fmaxf((x - m4.w) * s + be4.w, 0.f); }

    __half2 h01 = __floats2half2_rn(o.x, o.y);
    __half2 h23 = __floats2half2_rn(o.z, o.w);
    uint2 st2;
    st2.x = *(u32*)&h01;
    st2.y = *(u32*)&h23;
    *(uint2*)(O + (size_t)node * 128 + j0) = st2;
}

// ---------------- plain GEMM: 64x128 tile, 2 CTAs/SM, fp16 out; HIN selects input dtype ----------------
#define G_AHI 0
#define G_ALO 16384
#define G_BHI 32768
#define G_BLO 65536
#define G_SMEM 98304

template <int HIN>
__global__ void __launch_bounds__(256, 2)
gemm_plain_kernel(const void* __restrict__ A, int widx, __half* __restrict__ C) {
    extern __shared__ char smem[];
    u32 sb = smem_u32(smem);
    int t = threadIdx.x;
    int wid = t >> 5;
    int l = t & 31;
    int r0 = blockIdx.x * 64;

    if (HIN) fill_A64h(smem, G_AHI, G_ALO, (const __half*)A, r0, t);
    else     fill_A64(smem, G_AHI, G_ALO, (const float*)A, r0, t);
    copy_B256(smem, G_BHI, G_BLO, widx, t);
    __syncthreads();

    int m0 = (wid & 1) * 32;
    int n0 = (wid >> 1) * 32;
    float acc[2][4][4];
    run_mainloop_m(sb + G_AHI, sb + G_ALO, sb + G_BHI, sb + G_BLO, m0, n0, l, acc);

    int crow = l >> 2;
    int ccol = (l & 3) * 2;
#pragma unroll
    for (int mf = 0; mf < 2; mf++) {
#pragma unroll
        for (int j = 0; j < 4; j++) {
            int row = m0 + mf * 16 + crow;
            int col = n0 + j * 8 + ccol;
            int gr = r0 + row;
            if (gr < NN)
                *(__half2*)(C + (size_t)gr * 128 + col) =
                    __floats2half2_rn(acc[mf][j][0], acc[mf][j][1]);
            if (gr + 8 < NN)
                *(__half2*)(C + (size_t)(gr + 8) * 128 + col) =
                    __floats2half2_rn(acc[mf][j][2], acc[mf][j][3]);
        }
    }
}

// ---------------- fused MLP: fp16 H input, B-plane swap; resets g_deg/g_blk at end ----------------
#define M_SC3  0
#define M_SH3  512
#define M_BF2  1024
#define M_WO   1536
#define M_AHI  2048
#define M_ALO  18432
#define M_BHI  34816
#define M_BLO  67584
#define M_C    34816
#define M_SMEM 100352

__global__ void __launch_bounds__(256, 2)
mlp_fused_kernel(const __half* __restrict__ H,
                 const float* __restrict__ bf1,
                 const float* __restrict__ g3, const float* __restrict__ be3,
                 const float* __restrict__ m3, const float* __restrict__ v3,
                 const float* __restrict__ bf2,
                 const float* __restrict__ Wo, const float* __restrict__ bo,
                 float* __restrict__ h1_out, float* __restrict__ pred) {
    extern __shared__ char smem[];
    u32 sb = smem_u32(smem);
    float* smf = (float*)smem;
    int t = threadIdx.x;
    int wid = t >> 5;
    int l = t & 31;
    int r0 = blockIdx.x * 64;

    // reset CSR-build state for the next run (consumed by agg2 already)
    {
        int i = blockIdx.x * 256 + t;
        if (i < NN) g_deg[i] = 0;
        if (blockIdx.x == 0 && t < 512) g_blk[t] = 0ull;
    }

    if (t < 128) {
        float s = g3[t] * rsqrtf(v3[t] + BN_EPS);
        smf[M_SC3 / 4 + t] = s;
        smf[M_SH3 / 4 + t] = (bf1[t] - m3[t]) * s + be3[t];
        smf[M_BF2 / 4 + t] = bf2[t];
        smf[M_WO / 4 + t]  = Wo[t];
    }
    copy_B256(smem, M_BHI, M_BLO, 2, t);   // Wf1
    fill_A64h(smem, M_AHI, M_ALO, H, r0, t);
    __syncthreads();

    int m0 = (wid & 1) * 32;
    int n0 = (wid >> 1) * 32;
    int crow = l >> 2;
    int ccol = (l & 3) * 2;

    float acc[2][4][4];
    run_mainloop_m(sb + M_AHI, sb + M_ALO, sb + M_BHI, sb + M_BLO, m0, n0, l, acc);
    __syncthreads();   // all warps done reading A + B1 planes

    // X3 = relu(acc*sc3 + sh3) -> rewrite A planes; swap in Wf2 planes
#pragma unroll
    for (int mf = 0; mf < 2; mf++) {
#pragma unroll
        for (int j = 0; j < 4; j++) {
            int row = m0 + mf * 16 + crow;
            int col = n0 + j * 8 + ccol;
            float sc0 = smf[M_SC3 / 4 + col],     sh0 = smf[M_SH3 / 4 + col];
            float sc1 = smf[M_SC3 / 4 + col + 1], sh1 = smf[M_SH3 / 4 + col + 1];
            float x0 = fmaxf(acc[mf][j][0] * sc0 + sh0, 0.f);
            float x1 = fmaxf(acc[mf][j][1] * sc1 + sh1, 0.f);
            float x2 = fmaxf(acc[mf][j][2] * sc0 + sh0, 0.f);
            float x3 = fmaxf(acc[mf][j][3] * sc1 + sh1, 0.f);
            u32 lo0, lo1;
            u32 hi0 = pack_hilo2(x0, x1, lo0);
            u32 hi1 = pack_hilo2(x2, x3, lo1);
            u32 cb = (u32)(col * 2);
            u32 off0 = (u32)(row * 256) + ((cb & ~15u) ^ ((u32)(row & 7) << 4)) + (cb & 15u);
            int row2 = row + 8;
            u32 off1 = (u32)(row2 * 256) + ((cb & ~15u) ^ ((u32)(row2 & 7) << 4)) + (cb & 15u);
            *(u32*)(smem + M_AHI + off0) = hi0;
            *(u32*)(smem + M_ALO + off0) = lo0;
            *(u32*)(smem + M_AHI + off1) = hi1;
            *(u32*)(smem + M_ALO + off1) = lo1;
        }
    }
    copy_B256(smem, M_BHI, M_BLO, 3, t);   // Wf2 over Wf1
    __syncthreads();

    run_mainloop_m(sb + M_AHI, sb + M_ALO, sb + M_BHI, sb + M_BLO, m0, n0, l, acc);
    __syncthreads();   // B planes reused as C staging

    // h1 = relu(acc + bf2), stage to C (512B rows, 16B-block swizzle)
#pragma unroll
    for (int mf = 0; mf < 2; mf++) {
#pragma unroll
        for (int j = 0; j < 4; j++) {
            int row = m0 + mf * 16 + crow;
            int col = n0 + j * 8 + ccol;
            float b0 = smf[M_BF2 / 4 + col], b1 = smf[M_BF2 / 4 + col + 1];
            float v0 = fmaxf(acc[mf][j][0] + b0, 0.f);
            float v1 = fmaxf(acc[mf][j][1] + b1, 0.f);
            float v2 = fmaxf(acc[mf][j][2] + b0, 0.f);
            float v3v = fmaxf(acc[mf][j][3] + b1, 0.f);
            u32 o1 = (u32)(row * 512) + (((u32)(col * 4)) ^ ((u32)(row & 7) << 4));
            *(float2*)(smem + M_C + o1) = make_float2(v0, v1);
            int row2 = row + 8;
            u32 o2 = (u32)(row2 * 512) + (((u32)(col * 4)) ^ ((u32)(row2 & 7) << 4));
            *(float2*)(smem + M_C + o2) = make_float2(v2, v3v);
        }
    }
    __syncthreads();

    // pred = softplus(h1 . Wo + bo)
    if (t < 64) {
        int gr = r0 + t;
        if (gr < NN) {
            float dot = bo[0];
#pragma unroll 8
            for (int c16 = 0; c16 < 32; c16++) {
                u32 off = (u32)(t * 512) + (((u32)(c16 * 16)) ^ ((u32)(t & 7) << 4));
                float4 hv = *(float4*)(smem + M_C + off);
                int col = c16 * 4;
                dot += hv.x * smf[M_WO / 4 + col] + hv.y * smf[M_WO / 4 + col + 1] +
                       hv.z * smf[M_WO / 4 + col + 2] + hv.w * smf[M_WO / 4 + col + 3];
            }
            pred[gr] = fmaxf(dot, 0.f) + log1pf(expf(-fabsf(dot)));  // logaddexp(dot,0)
        }
    }

    // coalesced h1 copy-out (fp32 — it is part of the output)
#pragma unroll
    for (int i = 0; i < 8; i++) {
        int lin = i * 256 + t;
        int row = lin >> 5;
        int c16 = lin & 31;
        int gr = r0 + row;
        if (gr >= NN) continue;
        u32 off = (u32)(row * 512) + (((u32)(c16 * 16)) ^ ((u32)(row & 7) << 4));
        float4 val = *(float4*)(smem + M_C + off);
        *(float4*)(h1_out + (size_t)gr * 128 + c16 * 4) = val;
    }
}

// ---------------- launcher ----------------
extern "C" void kernel_launch(void* const* d_in, const int* in_sizes, int n_in,
                              void* d_out, int out_size) {
    const float* x   = (const float*)d_in[0];
    const void*  ei  = d_in[1];
    const float* W1  = (const float*)d_in[2];
    const float* b1  = (const float*)d_in[3];
    const float* W2  = (const float*)d_in[4];
    const float* b2  = (const float*)d_in[5];
    const float* Wf1 = (const float*)d_in[6];
    const float* bf1 = (const float*)d_in[7];
    const float* Wf2 = (const float*)d_in[8];
    const float* bf2 = (const float*)d_in[9];
    const float* Wo  = (const float*)d_in[10];
    const float* bo  = (const float*)d_in[11];
    const float* g1  = (const float*)d_in[12];
    const float* be1 = (const float*)d_in[13];
    const float* m1  = (const float*)d_in[14];
    const float* v1  = (const float*)d_in[15];
    const float* g2  = (const float*)d_in[16];
    const float* be2 = (const float*)d_in[17];
    const float* m2  = (const float*)d_in[18];
    const float* v2  = (const float*)d_in[19];
    const float* g3  = (const float*)d_in[20];
    const float* be3 = (const float*)d_in[21];
    const float* m3  = (const float*)d_in[22];
    const float* v3  = (const float*)d_in[23];

    float* out = (float*)d_out;
    float* h1_out = out + NN;    // output layout: (raw_pred[N], h1[N,128])

    float *bufA = nullptr, *bufB = nullptr;
    cudaGetSymbolAddress((void**)&bufA, g_bufA);
    cudaGetSymbolAddress((void**)&bufB, g_bufB);
    __half* P = (__half*)bufA;   // fp16 projections
    __half* Hh = (__half*)bufB;  // fp16 hidden

    cudaFuncSetAttribute((const void*)gemm_plain_kernel<0>,
                         cudaFuncAttributeMaxDynamicSharedMemorySize, G_SMEM);
    cudaFuncSetAttribute((const void*)gemm_plain_kernel<1>,
                         cudaFuncAttributeMaxDynamicSharedMemorySize, G_SMEM);
    cudaFuncSetAttribute((const void*)mlp_fused_kernel,
                         cudaFuncAttributeMaxDynamicSharedMemorySize, M_SMEM);

    // lazily created host-side resources (no device memory involved)
    static cudaStream_t s2 = nullptr;
    static cudaEvent_t evFork = nullptr, evJoin = nullptr;
    if (!s2) {
        cudaStreamCreateWithFlags(&s2, cudaStreamNonBlocking);
        cudaEventCreateWithFlags(&evFork, cudaEventDisableTiming);
        cudaEventCreateWithFlags(&evJoin, cudaEventDisableTiming);
    }

    const int NB = NB_SCAN;                    // 391
    const int EB8 = (EE + 2047) / 2048;        // 8 edges/thread -> 782 blocks
    const int GB = (NN + 63) / 64;             // 1563
    const int AB = (NN + 7) / 8;               // warp per node

    // fork: s2 runs wplanes + gemm1 concurrent with the CSR chain on stream 0.
    // submission order: degdet(0), wplanes(1), scan_lb(2), fill(3) <- profiled, gemm1(4)
    cudaEventRecord(evFork, 0);
    cudaStreamWaitEvent(s2, evFork, 0);

    degdet_kernel<<<NB, 256>>>(ei);                             // 0 (s0)
    wplanes_kernel<<<4, 256, 0, s2>>>(W1, W2, Wf1, Wf2);        // 1 (s2)
    scan_lb_kernel<<<NB, 256>>>();                              // 2 (s0)
    fill_kernel<<<EB8, 256>>>(ei);                              // 3 (s0)  <- ncu
    gemm_plain_kernel<0><<<GB, 256, G_SMEM, s2>>>(x, 0, P);     // 4 (s2)
    cudaEventRecord(evJoin, s2);

    // join, then the serial tail
    cudaStreamWaitEvent(0, evJoin, 0);
    agg_kernel<<<AB, 256>>>(P, Hh, b1, g1, be1, m1, v1);        // 5
    gemm_plain_kernel<1><<<GB, 256, G_SMEM>>>(Hh, 1, P);        // 6
    agg_kernel<<<AB, 256>>>(P, Hh, b2, g2, be2, m2, v2);        // 7
    mlp_fused_kernel<<<GB, 256, M_SMEM>>>(Hh, bf1, g3, be3, m3, v3,
                                          bf2, Wo, bo, h1_out, out); // 8
}

// round 16
// speedup vs baseline: 1.0320x; 1.0320x over previous
#include <cuda_runtime.h>
#include <cuda_bf16.h>
#include <cuda_fp16.h>
#include <math.h>

#define NN 100000
#define EE 1600000
#define HID 128
#define BN_EPS 1e-5f
#define NB_SCAN 391   // ceil(NN/256)

typedef unsigned long long ull;
typedef unsigned int u32;

// ---------------- scratch (no allocations allowed) ----------------
__device__ float g_bufA[(size_t)NN * HID];   // fp16 P lives here
__device__ float g_bufB[(size_t)NN * HID];   // fp16 H lives here
__device__ int   g_deg[NN];                  // zeroed at END of each run (and at load)
__device__ int   g_off[NN];
__device__ int   g_cur[NN];
__device__ float g_dinv[NN];
__device__ int   g_csr[EE];
__device__ int   g_bsum[1024];
__device__ int   g_is64;
__device__ char  g_wplanes[4 * 65536];       // 4 W matrices x (hi 32KB + lo 32KB)

// ---------------- helpers ----------------
__device__ __forceinline__ u32 smem_u32(const void* p) {
    u32 a;
    asm("{ .reg .u64 t; cvta.to.shared.u64 t, %1; cvt.u32.u64 %0, t; }" : "=r"(a) : "l"(p));
    return a;
}

__device__ __forceinline__ void ldsm4(u32 addr, u32* r) {
    asm volatile("ldmatrix.sync.aligned.m8n8.x4.shared.b16 {%0,%1,%2,%3}, [%4];"
        : "=r"(r[0]), "=r"(r[1]), "=r"(r[2]), "=r"(r[3]) : "r"(addr));
}

__device__ __forceinline__ void mma_bf16(float* c, const u32* a, u32 b0, u32 b1) {
    asm volatile("mma.sync.aligned.m16n8k16.row.col.f32.bf16.bf16.f32 "
        "{%0,%1,%2,%3}, {%4,%5,%6,%7}, {%8,%9}, {%0,%1,%2,%3};"
        : "+f"(c[0]), "+f"(c[1]), "+f"(c[2]), "+f"(c[3])
        : "r"(a[0]), "r"(a[1]), "r"(a[2]), "r"(a[3]), "r"(b0), "r"(b1));
}

__device__ __forceinline__ void split8(const float* f, uint4& hi, uint4& lo) {
    unsigned short h[8], l[8];
#pragma unroll
    for (int j = 0; j < 8; j++) {
        __nv_bfloat16 bh = __float2bfloat16(f[j]);
        float fh = __bfloat162float(bh);
        __nv_bfloat16 bl = __float2bfloat16(f[j] - fh);
        h[j] = __bfloat16_as_ushort(bh);
        l[j] = __bfloat16_as_ushort(bl);
    }
    hi.x = (u32)h[0] | ((u32)h[1] << 16); hi.y = (u32)h[2] | ((u32)h[3] << 16);
    hi.z = (u32)h[4] | ((u32)h[5] << 16); hi.w = (u32)h[6] | ((u32)h[7] << 16);
    lo.x = (u32)l[0] | ((u32)l[1] << 16); lo.y = (u32)l[2] | ((u32)l[3] << 16);
    lo.z = (u32)l[4] | ((u32)l[5] << 16); lo.w = (u32)l[6] | ((u32)l[7] << 16);
}

__device__ __forceinline__ u32 pack_hilo2(float x0, float x1, u32& lo) {
    __nv_bfloat16 h0 = __float2bfloat16(x0);
    __nv_bfloat16 l0 = __float2bfloat16(x0 - __bfloat162float(h0));
    __nv_bfloat16 h1 = __float2bfloat16(x1);
    __nv_bfloat16 l1 = __float2bfloat16(x1 - __bfloat162float(h1));
    lo = (u32)__bfloat16_as_ushort(l0) | ((u32)__bfloat16_as_ushort(l1) << 16);
    return (u32)__bfloat16_as_ushort(h0) | ((u32)__bfloat16_as_ushort(h1) << 16);
}

__device__ __forceinline__ int edge_at(const void* ei, long long i, int is64) {
    if (is64) return (int)((const long long*)ei)[i];
    return ((const int*)ei)[i];
}

// fp16 row fragment load (4 cols = 8 bytes)
__device__ __forceinline__ float4 ldrow_h(const __half* __restrict__ P, size_t row, int j0) {
    uint2 r = *(const uint2*)(P + row * 128 + j0);
    __half2 h0 = *reinterpret_cast<__half2*>(&r.x);
    __half2 h1 = *reinterpret_cast<__half2*>(&r.y);
    float2 f0 = __half22float2(h0), f1 = __half22float2(h1);
    return make_float4(f0.x, f0.y, f1.x, f1.y);
}

// ---------------- pipelined mainloop: warp tile 32x32, split-bf16 (3 products) ----------------
// AH/AL/BH fragments are double-buffered one k-step ahead; BL is loaded at iteration
// start and consumed only by the trailing 8 MMAs (self-hiding latency).
__device__ __forceinline__ void run_mainloop_p(u32 AHIb, u32 ALOb, u32 BHIb, u32 BLOb,
                                               int m0, int n0, int l, float acc[2][4][4]) {
    int quad = l >> 3;
    int aRow0 = m0 + (l & 7) + ((quad & 1) << 3);
    int aKsel = (quad >> 1) << 4;
    u32 axor = (u32)((aRow0 & 7) << 4);
    u32 arb0 = (u32)(aRow0 * 256);
    u32 arb1 = (u32)((aRow0 + 16) * 256);

    int bRow0 = n0 + (l & 7) + ((quad >> 1) << 3);
    int bKsel = (quad & 1) << 4;
    u32 bxor = (u32)((bRow0 & 7) << 4);
    u32 brb0 = (u32)(bRow0 * 256);
    u32 brb1 = (u32)((bRow0 + 16) * 256);

#pragma unroll
    for (int mf = 0; mf < 2; mf++)
#pragma unroll
        for (int j = 0; j < 4; j++)
#pragma unroll
            for (int k = 0; k < 4; k++) acc[mf][j][k] = 0.f;

    u32 AH0[2][4], AH1[2][4], AL0[2][4], AL1[2][4], BH0[2][4], BH1[2][4];

    {   // prologue: ks = 0 into buffer 0
        u32 kbA = (u32)aKsel ^ axor;
        u32 kbB = (u32)bKsel ^ bxor;
        ldsm4(AHIb + arb0 + kbA, AH0[0]);
        ldsm4(AHIb + arb1 + kbA, AH1[0]);
        ldsm4(ALOb + arb0 + kbA, AL0[0]);
        ldsm4(ALOb + arb1 + kbA, AL1[0]);
        ldsm4(BHIb + brb0 + kbB, BH0[0]);
        ldsm4(BHIb + brb1 + kbB, BH1[0]);
    }

#pragma unroll
    for (int ks = 0; ks < 8; ks++) {
        const int cur = ks & 1, nxt = cur ^ 1;
        u32 kbB = (u32)(ks * 32 + bKsel) ^ bxor;
        u32 bl0[4], bl1[4];
        ldsm4(BLOb + brb0 + kbB, bl0);
        ldsm4(BLOb + brb1 + kbB, bl1);
        if (ks < 7) {
            u32 kbA2 = (u32)((ks + 1) * 32 + aKsel) ^ axor;
            u32 kbB2 = (u32)((ks + 1) * 32 + bKsel) ^ bxor;
            ldsm4(AHIb + arb0 + kbA2, AH0[nxt]);
            ldsm4(AHIb + arb1 + kbA2, AH1[nxt]);
            ldsm4(ALOb + arb0 + kbA2, AL0[nxt]);
            ldsm4(ALOb + arb1 + kbA2, AL1[nxt]);
            ldsm4(BHIb + brb0 + kbB2, BH0[nxt]);
            ldsm4(BHIb + brb1 + kbB2, BH1[nxt]);
        }
        // hi-path: AH x BH + AL x BH (fragments preloaded last iteration)
#pragma unroll
        for (int j = 0; j < 4; j++) {
            u32 h0 = (j < 2 ? BH0[cur] : BH1[cur])[(j & 1) * 2];
            u32 h1 = (j < 2 ? BH0[cur] : BH1[cur])[(j & 1) * 2 + 1];
            mma_bf16(acc[0][j], AH0[cur], h0, h1);
            mma_bf16(acc[1][j], AH1[cur], h0, h1);
            mma_bf16(acc[0][j], AL0[cur], h0, h1);
            mma_bf16(acc[1][j], AL1[cur], h0, h1);
        }
        // lo-path: AH x BL (bl just loaded; latency covered by the 16 MMAs above)
#pragma unroll
        for (int j = 0; j < 4; j++) {
            u32 l0 = (j < 2 ? bl0 : bl1)[(j & 1) * 2];
            u32 l1 = (j < 2 ? bl0 : bl1)[(j & 1) * 2 + 1];
            mma_bf16(acc[0][j], AH0[cur], l0, l1);
            mma_bf16(acc[1][j], AH1[cur], l0, l1);
        }
    }
}

// fill A planes: 64 rows, 256 threads, fp32 source
__device__ __forceinline__ void fill_A64(char* smem, int OFF_HI, int OFF_LO,
                                         const float* __restrict__ A, int r0, int t) {
#pragma unroll
    for (int i = 0; i < 4; i++) {
        int q = i * 256 + t;
        int r = q >> 4;
        int c = q & 15;
        int gr = r0 + r;
        uint4 hi, lo;
        if (gr < NN) {
            float f[8];
            float4 a0 = *(const float4*)(A + (size_t)gr * 128 + c * 8);
            float4 a1 = *(const float4*)(A + (size_t)gr * 128 + c * 8 + 4);
            f[0] = a0.x; f[1] = a0.y; f[2] = a0.z; f[3] = a0.w;
            f[4] = a1.x; f[5] = a1.y; f[6] = a1.z; f[7] = a1.w;
            split8(f, hi, lo);
        } else {
            hi = make_uint4(0, 0, 0, 0);
            lo = make_uint4(0, 0, 0, 0);
        }
        u32 off = r * 256 + ((c * 16) ^ ((r & 7) << 4));
        *(uint4*)(smem + OFF_HI + off) = hi;
        *(uint4*)(smem + OFF_LO + off) = lo;
    }
}

// fill A planes: 64 rows, 256 threads, fp16 source
__device__ __forceinline__ void fill_A64h(char* smem, int OFF_HI, int OFF_LO,
                                          const __half* __restrict__ A, int r0, int t) {
#pragma unroll
    for (int i = 0; i < 4; i++) {
        int q = i * 256 + t;
        int r = q >> 4;
        int c = q & 15;
        int gr = r0 + r;
        uint4 hi, lo;
        if (gr < NN) {
            uint4 raw = *(const uint4*)(A + (size_t)gr * 128 + c * 8);  // 8 halfs = 16B
            __half2* hp = (__half2*)&raw;
            float f[8];
#pragma unroll
            for (int j = 0; j < 4; j++) {
                float2 fv = __half22float2(hp[j]);
                f[2 * j] = fv.x;
                f[2 * j + 1] = fv.y;
            }
            split8(f, hi, lo);
        } else {
            hi = make_uint4(0, 0, 0, 0);
            lo = make_uint4(0, 0, 0, 0);
        }
        u32 off = r * 256 + ((c * 16) ^ ((r & 7) << 4));
        *(uint4*)(smem + OFF_HI + off) = hi;
        *(uint4*)(smem + OFF_LO + off) = lo;
    }
}

// copy precomputed W planes (64 KB) into smem with 256 threads
__device__ __forceinline__ void copy_B256(char* smem, int OFF_HI, int OFF_LO,
                                          int widx, int t) {
    const uint4* src = (const uint4*)(g_wplanes + widx * 65536);
#pragma unroll
    for (int i = 0; i < 8; i++) {
        int idx = i * 256 + t;
        ((uint4*)(smem + OFF_HI))[idx] = src[idx];
        ((uint4*)(smem + OFF_LO))[idx] = src[2048 + idx];
    }
}

// ---------------- W planes (4 blocks) ----------------
__global__ void wplanes_kernel(const float* __restrict__ W1, const float* __restrict__ W2,
                               const float* __restrict__ Wf1, const float* __restrict__ Wf2) {
    const float* W = (blockIdx.x == 0) ? W1 : (blockIdx.x == 1) ? W2 :
                     (blockIdx.x == 2) ? Wf1 : Wf2;
    char* dst = g_wplanes + blockIdx.x * 65536;
    int t = threadIdx.x;
#pragma unroll
    for (int i = 0; i < 8; i++) {
        int q = i * 256 + t;
        int n = q & 127;
        int kb = q >> 7;
        float f[8];
#pragma unroll
        for (int j = 0; j < 8; j++) f[j] = W[(kb * 8 + j) * 128 + n];
        uint4 hi, lo;
        split8(f, hi, lo);
        u32 off = n * 256 + ((kb * 16) ^ ((n & 7) << 4));
        *(uint4*)(dst + off) = hi;
        *(uint4*)(dst + 32768 + off) = lo;
    }
}

// ---------------- dtype detect + degree histogram (4-wide grid-stride) ----------------
// Requires g_deg == 0 on entry (zeroed at load and at END of each run by mlp).
__global__ void degdet_kernel(const void* __restrict__ ei) {
    int b = blockIdx.x, t = threadIdx.x;
    __shared__ int nz;
    if (t == 0) nz = 0;
    __syncthreads();
    const int* ei32 = (const int*)ei;
    int bad = 0;
    for (int j = t; j < 2048; j += 256)
        if (ei32[2 * j + 1] != 0) bad = 1;
    if (bad) atomicOr(&nz, 1);
    __syncthreads();
    int is64 = (nz == 0) ? 1 : 0;
    if (b == 0 && t == 0) g_is64 = is64;

    const long long S = (long long)NB_SCAN * 256;
    long long e = (long long)b * 256 + t;
    for (; e + 3 * S < EE; e += 4 * S) {
        int d0 = edge_at(ei, EE + e, is64);
        int d1 = edge_at(ei, EE + e + S, is64);
        int d2 = edge_at(ei, EE + e + 2 * S, is64);
        int d3 = edge_at(ei, EE + e + 3 * S, is64);
        atomicAdd(&g_deg[d0], 1);
        atomicAdd(&g_deg[d1], 1);
        atomicAdd(&g_deg[d2], 1);
        atomicAdd(&g_deg[d3], 1);
    }
    for (; e < EE; e += S) {
        int d = edge_at(ei, EE + e, is64);
        atomicAdd(&g_deg[d], 1);
    }
}

// ---------------- scans ----------------
__global__ void scan1_kernel() {
    __shared__ int sm[256];
    int i = blockIdx.x * 256 + threadIdx.x;
    int v = (i < NN) ? g_deg[i] : 0;
    sm[threadIdx.x] = v;
    __syncthreads();
    for (int s = 1; s < 256; s <<= 1) {
        int add = (threadIdx.x >= (unsigned)s) ? sm[threadIdx.x - s] : 0;
        __syncthreads();
        sm[threadIdx.x] += add;
        __syncthreads();
    }
    if (i < NN) g_off[i] = sm[threadIdx.x];
    if (threadIdx.x == 255) g_bsum[blockIdx.x] = sm[255];
}

__global__ void scan2b_kernel() {
    __shared__ int sm[512];
    int t = threadIdx.x;
    sm[t] = (t < NB_SCAN) ? g_bsum[t] : 0;
    __syncthreads();
    for (int s = 1; s < 512; s <<= 1) {
        int add = (t >= s) ? sm[t - s] : 0;
        __syncthreads();
        sm[t] += add;
        __syncthreads();
    }
    if (t < 256) {
        int i = blockIdx.x * 256 + t;
        if (i < NN) {
            int base = (blockIdx.x > 0) ? sm[blockIdx.x - 1] : 0;
            int d = g_deg[i];
            int excl = base + g_off[i] - d;
            g_off[i] = excl;
            g_cur[i] = excl;
            g_dinv[i] = rsqrtf((float)(d + 1));
        }
    }
}

// ---------------- CSR fill (4 edges per thread — proven best) ----------------
__global__ void fill_kernel(const void* __restrict__ ei) {
    int base = (blockIdx.x * blockDim.x + threadIdx.x) * 4;
    int is64 = g_is64;
    int s[4], d[4];
#pragma unroll
    for (int u = 0; u < 4; u++) {
        if (base + u < EE) {
            s[u] = edge_at(ei, base + u, is64);
            d[u] = edge_at(ei, (long long)EE + base + u, is64);
        } else {
            s[u] = -1;
        }
    }
#pragma unroll
    for (int u = 0; u < 4; u++) {
        if (s[u] >= 0) {
            int pos = atomicAdd(&g_cur[d[u]], 1);
            g_csr[pos] = s[u];
        }
    }
}

// ---------------- aggregation: gather fp16 P -> fp32 accum -> fp16 out ----------------
__global__ void agg_kernel(const __half* __restrict__ P, __half* __restrict__ O,
                           const float* __restrict__ bias,
                           const float* __restrict__ g, const float* __restrict__ be,
                           const float* __restrict__ m, const float* __restrict__ v) {
    int node = (blockIdx.x * blockDim.x + threadIdx.x) >> 5;
    int lane = threadIdx.x & 31;
    if (node >= NN) return;
    float dn = g_dinv[node];
    int j0 = lane * 4;

    float4 self = ldrow_h(P, (size_t)node, j0);
    float4 acc;
    acc.x = self.x * dn;
    acc.y = self.y * dn;
    acc.z = self.z * dn;
    acc.w = self.w * dn;

    int st = g_off[node];
    int en = st + g_deg[node];
    int e = st;
    for (; e + 8 <= en; e += 8) {
        int s0 = g_csr[e],     s1 = g_csr[e + 1], s2 = g_csr[e + 2], s3 = g_csr[e + 3];
        int s4 = g_csr[e + 4], s5 = g_csr[e + 5], s6 = g_csr[e + 6], s7 = g_csr[e + 7];
        float w0 = g_dinv[s0], w1 = g_dinv[s1], w2 = g_dinv[s2], w3 = g_dinv[s3];
        float w4 = g_dinv[s4], w5 = g_dinv[s5], w6 = g_dinv[s6], w7 = g_dinv[s7];
        float4 p0 = ldrow_h(P, (size_t)s0, j0);
        float4 p1 = ldrow_h(P, (size_t)s1, j0);
        float4 p2 = ldrow_h(P, (size_t)s2, j0);
        float4 p3 = ldrow_h(P, (size_t)s3, j0);
        float4 p4 = ldrow_h(P, (size_t)s4, j0);
        float4 p5 = ldrow_h(P, (size_t)s5, j0);
        float4 p6 = ldrow_h(P, (size_t)s6, j0);
        float4 p7 = ldrow_h(P, (size_t)s7, j0);
        acc.x += p0.x * w0 + p1.x * w1 + p2.x * w2 + p3.x * w3 +
                 p4.x * w4 + p5.x * w5 + p6.x * w6 + p7.x * w7;
        acc.y += p0.y * w0 + p1.y * w1 + p2.y * w2 + p3.y * w3 +
                 p4.y * w4 + p5.y * w5 + p6.y * w6 + p7.y * w7;
        acc.z += p0.z * w0 + p1.z * w1 + p2.z * w2 + p3.z * w3 +
                 p4.z * w4 + p5.z * w5 + p6.z * w6 + p7.z * w7;
        acc.w += p0.w * w0 + p1.w * w1 + p2.w * w2 + p3.w * w3 +
                 p4.w * w4 + p5.w * w5 + p6.w * w6 + p7.w * w7;
    }
    for (; e + 4 <= en; e += 4) {
        int s0 = g_csr[e], s1 = g_csr[e + 1], s2 = g_csr[e + 2], s3 = g_csr[e + 3];
        float w0 = g_dinv[s0], w1 = g_dinv[s1], w2 = g_dinv[s2], w3 = g_dinv[s3];
        float4 p0 = ldrow_h(P, (size_t)s0, j0);
        float4 p1 = ldrow_h(P, (size_t)s1, j0);
        float4 p2 = ldrow_h(P, (size_t)s2, j0);
        float4 p3 = ldrow_h(P, (size_t)s3, j0);
        acc.x += p0.x * w0 + p1.x * w1 + p2.x * w2 + p3.x * w3;
        acc.y += p0.y * w0 + p1.y * w1 + p2.y * w2 + p3.y * w3;
        acc.z += p0.z * w0 + p1.z * w1 + p2.z * w2 + p3.z * w3;
        acc.w += p0.w * w0 + p1.w * w1 + p2.w * w2 + p3.w * w3;
    }
    for (; e < en; e++) {
        int s = g_csr[e];
        float w = g_dinv[s];
        float4 p = ldrow_h(P, (size_t)s, j0);
        acc.x += p.x * w;
        acc.y += p.y * w;
        acc.z += p.z * w;
        acc.w += p.w * w;
    }

    float4 b4  = *(const float4*)(bias + j0);
    float4 g4  = *(const float4*)(g + j0);
    float4 be4 = *(const float4*)(be + j0);
    float4 m4  = *(const float4*)(m + j0);
    float4 v4  = *(const float4*)(v + j0);

    float4 o;
    { float x = acc.x * dn + b4.x; float s = g4.x * rsqrtf(v4.x + BN_EPS); o.x = fmaxf((x - m4.x) * s + be4.x, 0.f); }
    { float x = acc.y * dn + b4.y; float s = g4.y * rsqrtf(v4.y + BN_EPS); o.y = fmaxf((x - m4.y) * s + be4.y, 0.f); }
    { float x = acc.z * dn + b4.z; float s = g4.z * rsqrtf(v4.z + BN_EPS); o.z = fmaxf((x - m4.z) * s + be4.z, 0.f); }
    { float x = acc.w * dn + b4.w; float s = g4.w * rsqrtf(v4.w + BN_EPS); o.w = fmaxf((x - m4.w) * s + be4.w, 0.f); }

    __half2 h01 = __floats2half2_rn(o.x, o.y);
    __half2 h23 = __floats2half2_rn(o.z, o.w);
    uint2 st2;
    st2.x = *(u32*)&h01;
    st2.y = *(u32*)&h23;
    *(uint2*)(O + (size_t)node * 128 + j0) = st2;
}

// ---------------- plain GEMM: 64x128 tile, 2 CTAs/SM, fp16 out; HIN selects input dtype ----------------
#define G_AHI 0
#define G_ALO 16384
#define G_BHI 32768
#define G_BLO 65536
#define G_SMEM 98304

template <int HIN>
__global__ void __launch_bounds__(256, 2)
gemm_plain_kernel(const void* __restrict__ A, int widx, __half* __restrict__ C) {
    extern __shared__ char smem[];
    u32 sb = smem_u32(smem);
    int t = threadIdx.x;
    int wid = t >> 5;
    int l = t & 31;
    int r0 = blockIdx.x * 64;

    if (HIN) fill_A64h(smem, G_AHI, G_ALO, (const __half*)A, r0, t);
    else     fill_A64(smem, G_AHI, G_ALO, (const float*)A, r0, t);
    copy_B256(smem, G_BHI, G_BLO, widx, t);
    __syncthreads();

    int m0 = (wid & 1) * 32;
    int n0 = (wid >> 1) * 32;
    float acc[2][4][4];
    run_mainloop_p(sb + G_AHI, sb + G_ALO, sb + G_BHI, sb + G_BLO, m0, n0, l, acc);

    int crow = l >> 2;
    int ccol = (l & 3) * 2;
#pragma unroll
    for (int mf = 0; mf < 2; mf++) {
#pragma unroll
        for (int j = 0; j < 4; j++) {
            int row = m0 + mf * 16 + crow;
            int col = n0 + j * 8 + ccol;
            int gr = r0 + row;
            if (gr < NN)
                *(__half2*)(C + (size_t)gr * 128 + col) =
                    __floats2half2_rn(acc[mf][j][0], acc[mf][j][1]);
            if (gr + 8 < NN)
                *(__half2*)(C + (size_t)(gr + 8) * 128 + col) =
                    __floats2half2_rn(acc[mf][j][2], acc[mf][j][3]);
        }
    }
}

// ---------------- fused MLP: fp16 H input, B-plane swap; resets g_deg at end ----------------
#define M_SC3  0
#define M_SH3  512
#define M_BF2  1024
#define M_WO   1536
#define M_AHI  2048
#define M_ALO  18432
#define M_BHI  34816
#define M_BLO  67584
#define M_C    34816
#define M_SMEM 100352

__global__ void __launch_bounds__(256, 2)
mlp_fused_kernel(const __half* __restrict__ H,
                 const float* __restrict__ bf1,
                 const float* __restrict__ g3, const float* __restrict__ be3,
                 const float* __restrict__ m3, const float* __restrict__ v3,
                 const float* __restrict__ bf2,
                 const float* __restrict__ Wo, const float* __restrict__ bo,
                 float* __restrict__ h1_out, float* __restrict__ pred) {
    extern __shared__ char smem[];
    u32 sb = smem_u32(smem);
    float* smf = (float*)smem;
    int t = threadIdx.x;
    int wid = t >> 5;
    int l = t & 31;
    int r0 = blockIdx.x * 64;

    // reset g_deg for the next run (agg2 already consumed it)
    {
        int i = blockIdx.x * 256 + t;
        if (i < NN) g_deg[i] = 0;
    }

    if (t < 128) {
        float s = g3[t] * rsqrtf(v3[t] + BN_EPS);
        smf[M_SC3 / 4 + t] = s;
        smf[M_SH3 / 4 + t] = (bf1[t] - m3[t]) * s + be3[t];
        smf[M_BF2 / 4 + t] = bf2[t];
        smf[M_WO / 4 + t]  = Wo[t];
    }
    copy_B256(smem, M_BHI, M_BLO, 2, t);   // Wf1
    fill_A64h(smem, M_AHI, M_ALO, H, r0, t);
    __syncthreads();

    int m0 = (wid & 1) * 32;
    int n0 = (wid >> 1) * 32;
    int crow = l >> 2;
    int ccol = (l & 3) * 2;

    float acc[2][4][4];
    run_mainloop_p(sb + M_AHI, sb + M_ALO, sb + M_BHI, sb + M_BLO, m0, n0, l, acc);
    __syncthreads();   // all warps done reading A + B1 planes

    // X3 = relu(acc*sc3 + sh3) -> rewrite A planes; swap in Wf2 planes
#pragma unroll
    for (int mf = 0; mf < 2; mf++) {
#pragma unroll
        for (int j = 0; j < 4; j++) {
            int row = m0 + mf * 16 + crow;
            int col = n0 + j * 8 + ccol;
            float sc0 = smf[M_SC3 / 4 + col],     sh0 = smf[M_SH3 / 4 + col];
            float sc1 = smf[M_SC3 / 4 + col + 1], sh1 = smf[M_SH3 / 4 + col + 1];
            float x0 = fmaxf(acc[mf][j][0] * sc0 + sh0, 0.f);
            float x1 = fmaxf(acc[mf][j][1] * sc1 + sh1, 0.f);
            float x2 = fmaxf(acc[mf][j][2] * sc0 + sh0, 0.f);
            float x3 = fmaxf(acc[mf][j][3] * sc1 + sh1, 0.f);
            u32 lo0, lo1;
            u32 hi0 = pack_hilo2(x0, x1, lo0);
            u32 hi1 = pack_hilo2(x2, x3, lo1);
            u32 cb = (u32)(col * 2);
            u32 off0 = (u32)(row * 256) + ((cb & ~15u) ^ ((u32)(row & 7) << 4)) + (cb & 15u);
            int row2 = row + 8;
            u32 off1 = (u32)(row2 * 256) + ((cb & ~15u) ^ ((u32)(row2 & 7) << 4)) + (cb & 15u);
            *(u32*)(smem + M_AHI + off0) = hi0;
            *(u32*)(smem + M_ALO + off0) = lo0;
            *(u32*)(smem + M_AHI + off1) = hi1;
            *(u32*)(smem + M_ALO + off1) = lo1;
        }
    }
    copy_B256(smem, M_BHI, M_BLO, 3, t);   // Wf2 over Wf1
    __syncthreads();

    run_mainloop_p(sb + M_AHI, sb + M_ALO, sb + M_BHI, sb + M_BLO, m0, n0, l, acc);
    __syncthreads();   // B planes reused as C staging

    // h1 = relu(acc + bf2), stage to C (512B rows, 16B-block swizzle)
#pragma unroll
    for (int mf = 0; mf < 2; mf++) {
#pragma unroll
        for (int j = 0; j < 4; j++) {
            int row = m0 + mf * 16 + crow;
            int col = n0 + j * 8 + ccol;
            float b0 = smf[M_BF2 / 4 + col], b1 = smf[M_BF2 / 4 + col + 1];
            float v0 = fmaxf(acc[mf][j][0] + b0, 0.f);
            float v1 = fmaxf(acc[mf][j][1] + b1, 0.f);
            float v2 = fmaxf(acc[mf][j][2] + b0, 0.f);
            float v3v = fmaxf(acc[mf][j][3] + b1, 0.f);
            u32 o1 = (u32)(row * 512) + (((u32)(col * 4)) ^ ((u32)(row & 7) << 4));
            *(float2*)(smem + M_C + o1) = make_float2(v0, v1);
            int row2 = row + 8;
            u32 o2 = (u32)(row2 * 512) + (((u32)(col * 4)) ^ ((u32)(row2 & 7) << 4));
            *(float2*)(smem + M_C + o2) = make_float2(v2, v3v);
        }
    }
    __syncthreads();

    // pred = softplus(h1 . Wo + bo)
    if (t < 64) {
        int gr = r0 + t;
        if (gr < NN) {
            float dot = bo[0];
#pragma unroll 8
            for (int c16 = 0; c16 < 32; c16++) {
                u32 off = (u32)(t * 512) + (((u32)(c16 * 16)) ^ ((u32)(t & 7) << 4));
                float4 hv = *(float4*)(smem + M_C + off);
                int col = c16 * 4;
                dot += hv.x * smf[M_WO / 4 + col] + hv.y * smf[M_WO / 4 + col + 1] +
                       hv.z * smf[M_WO / 4 + col + 2] + hv.w * smf[M_WO / 4 + col + 3];
            }
            pred[gr] = fmaxf(dot, 0.f) + log1pf(expf(-fabsf(dot)));  // logaddexp(dot,0)
        }
    }

    // coalesced h1 copy-out (fp32 — it is part of the output)
#pragma unroll
    for (int i = 0; i < 8; i++) {
        int lin = i * 256 + t;
        int row = lin >> 5;
        int c16 = lin & 31;
        int gr = r0 + row;
        if (gr >= NN) continue;
        u32 off = (u32)(row * 512) + (((u32)(c16 * 16)) ^ ((u32)(row & 7) << 4));
        float4 val = *(float4*)(smem + M_C + off);
        *(float4*)(h1_out + (size_t)gr * 128 + c16 * 4) = val;
    }
}

// ---------------- launcher ----------------
extern "C" void kernel_launch(void* const* d_in, const int* in_sizes, int n_in,
                              void* d_out, int out_size) {
    const float* x   = (const float*)d_in[0];
    const void*  ei  = d_in[1];
    const float* W1  = (const float*)d_in[2];
    const float* b1  = (const float*)d_in[3];
    const float* W2  = (const float*)d_in[4];
    const float* b2  = (const float*)d_in[5];
    const float* Wf1 = (const float*)d_in[6];
    const float* bf1 = (const float*)d_in[7];
    const float* Wf2 = (const float*)d_in[8];
    const float* bf2 = (const float*)d_in[9];
    const float* Wo  = (const float*)d_in[10];
    const float* bo  = (const float*)d_in[11];
    const float* g1  = (const float*)d_in[12];
    const float* be1 = (const float*)d_in[13];
    const float* m1  = (const float*)d_in[14];
    const float* v1  = (const float*)d_in[15];
    const float* g2  = (const float*)d_in[16];
    const float* be2 = (const float*)d_in[17];
    const float* m2  = (const float*)d_in[18];
    const float* v2  = (const float*)d_in[19];
    const float* g3  = (const float*)d_in[20];
    const float* be3 = (const float*)d_in[21];
    const float* m3  = (const float*)d_in[22];
    const float* v3  = (const float*)d_in[23];

    float* out = (float*)d_out;
    float* h1_out = out + NN;    // output layout: (raw_pred[N], h1[N,128])

    float *bufA = nullptr, *bufB = nullptr;
    cudaGetSymbolAddress((void**)&bufA, g_bufA);
    cudaGetSymbolAddress((void**)&bufB, g_bufB);
    __half* P = (__half*)bufA;   // fp16 projections
    __half* Hh = (__half*)bufB;  // fp16 hidden

    cudaFuncSetAttribute((const void*)gemm_plain_kernel<0>,
                         cudaFuncAttributeMaxDynamicSharedMemorySize, G_SMEM);
    cudaFuncSetAttribute((const void*)gemm_plain_kernel<1>,
                         cudaFuncAttributeMaxDynamicSharedMemorySize, G_SMEM);
    cudaFuncSetAttribute((const void*)mlp_fused_kernel,
                         cudaFuncAttributeMaxDynamicSharedMemorySize, M_SMEM);

    // lazily created host-side resources (no device memory involved);
    // fall back to single-stream if creation fails for any reason
    static cudaStream_t s2 = nullptr;
    static cudaEvent_t evFork = nullptr, evJoin = nullptr;
    static int ok = -1;
    if (ok < 0) {
        ok = 1;
        if (cudaStreamCreateWithFlags(&s2, cudaStreamNonBlocking) != cudaSuccess) ok = 0;
        if (ok && cudaEventCreateWithFlags(&evFork, cudaEventDisableTiming) != cudaSuccess) ok = 0;
        if (ok && cudaEventCreateWithFlags(&evJoin, cudaEventDisableTiming) != cudaSuccess) ok = 0;
    }

    const int NB = NB_SCAN;                    // 391
    const int EB4 = (EE + 1023) / 1024;        // 4 edges/thread
    const int GB = (NN + 63) / 64;             // 1563
    const int AB = (NN + 7) / 8;               // warp per node

    cudaStream_t sW = ok ? s2 : (cudaStream_t)0;   // side stream (or default if unavailable)

    // fork: sW runs wplanes + gemm1 concurrent with the CSR chain on stream 0.
    // submission order: degdet(0), scan1(1), wplanes(2), gemm1(3) <- profiled,
    //                   scan2b(4), fill(5), then join + tail
    if (ok) {
        cudaEventRecord(evFork, 0);
        cudaStreamWaitEvent(s2, evFork, 0);
    }

    degdet_kernel<<<NB, 256>>>(ei);                             // 0 (s0)
    scan1_kernel<<<NB, 256>>>();                                // 1 (s0)
    wplanes_kernel<<<4, 256, 0, sW>>>(W1, W2, Wf1, Wf2);        // 2 (sW)
    gemm_plain_kernel<0><<<GB, 256, G_SMEM, sW>>>(x, 0, P);     // 3 (sW) <- ncu
    scan2b_kernel<<<NB, 512>>>();                               // 4 (s0)
    fill_kernel<<<EB4, 256>>>(ei);                              // 5 (s0)

    if (ok) {
        cudaEventRecord(evJoin, s2);
        cudaStreamWaitEvent(0, evJoin, 0);
    }
    agg_kernel<<<AB, 256>>>(P, Hh, b1, g1, be1, m1, v1);        // 6
    gemm_plain_kernel<1><<<GB, 256, G_SMEM>>>(Hh, 1, P);        // 7
    agg_kernel<<<AB, 256>>>(P, Hh, b2, g2, be2, m2, v2);        // 8
    mlp_fused_kernel<<<GB, 256, M_SMEM>>>(Hh, bf1, g3, be3, m3, v3,
                                          bf2, Wo, bo, h1_out, out); // 9
}

// round 17
// speedup vs baseline: 1.0703x; 1.0371x over previous
#include <cuda_runtime.h>
#include <cuda_bf16.h>
#include <cuda_fp16.h>
#include <math.h>

#define NN 100000
#define EE 1600000
#define HID 128
#define BN_EPS 1e-5f
#define NB_SCAN 391   // ceil(NN/256)

typedef unsigned long long ull;
typedef unsigned int u32;

// ---------------- scratch (no allocations allowed) ----------------
__device__ float g_bufA[(size_t)NN * HID];   // fp16 P lives here
__device__ float g_bufB[(size_t)NN * HID];   // fp16 H lives here
__device__ int   g_deg[NN];                  // zeroed at END of each run (and at load)
__device__ int   g_off[NN];
__device__ int   g_cur[NN];
__device__ float g_dinv[NN];
__device__ int   g_csr[EE];
__device__ int   g_bsum[1024];
__device__ int   g_is64;
__device__ char  g_wplanes[4 * 65536];       // 4 W matrices x (hi 32KB + lo 32KB)

// ---------------- helpers ----------------
__device__ __forceinline__ u32 smem_u32(const void* p) {
    u32 a;
    asm("{ .reg .u64 t; cvta.to.shared.u64 t, %1; cvt.u32.u64 %0, t; }" : "=r"(a) : "l"(p));
    return a;
}

__device__ __forceinline__ void ldsm4(u32 addr, u32* r) {
    asm volatile("ldmatrix.sync.aligned.m8n8.x4.shared.b16 {%0,%1,%2,%3}, [%4];"
        : "=r"(r[0]), "=r"(r[1]), "=r"(r[2]), "=r"(r[3]) : "r"(addr));
}

__device__ __forceinline__ void mma_bf16(float* c, const u32* a, u32 b0, u32 b1) {
    asm volatile("mma.sync.aligned.m16n8k16.row.col.f32.bf16.bf16.f32 "
        "{%0,%1,%2,%3}, {%4,%5,%6,%7}, {%8,%9}, {%0,%1,%2,%3};"
        : "+f"(c[0]), "+f"(c[1]), "+f"(c[2]), "+f"(c[3])
        : "r"(a[0]), "r"(a[1]), "r"(a[2]), "r"(a[3]), "r"(b0), "r"(b1));
}

__device__ __forceinline__ void split8(const float* f, uint4& hi, uint4& lo) {
    unsigned short h[8], l[8];
#pragma unroll
    for (int j = 0; j < 8; j++) {
        __nv_bfloat16 bh = __float2bfloat16(f[j]);
        float fh = __bfloat162float(bh);
        __nv_bfloat16 bl = __float2bfloat16(f[j] - fh);
        h[j] = __bfloat16_as_ushort(bh);
        l[j] = __bfloat16_as_ushort(bl);
    }
    hi.x = (u32)h[0] | ((u32)h[1] << 16); hi.y = (u32)h[2] | ((u32)h[3] << 16);
    hi.z = (u32)h[4] | ((u32)h[5] << 16); hi.w = (u32)h[6] | ((u32)h[7] << 16);
    lo.x = (u32)l[0] | ((u32)l[1] << 16); lo.y = (u32)l[2] | ((u32)l[3] << 16);
    lo.z = (u32)l[4] | ((u32)l[5] << 16); lo.w = (u32)l[6] | ((u32)l[7] << 16);
}

__device__ __forceinline__ u32 pack_hilo2(float x0, float x1, u32& lo) {
    __nv_bfloat16 h0 = __float2bfloat16(x0);
    __nv_bfloat16 l0 = __float2bfloat16(x0 - __bfloat162float(h0));
    __nv_bfloat16 h1 = __float2bfloat16(x1);
    __nv_bfloat16 l1 = __float2bfloat16(x1 - __bfloat162float(h1));
    lo = (u32)__bfloat16_as_ushort(l0) | ((u32)__bfloat16_as_ushort(l1) << 16);
    return (u32)__bfloat16_as_ushort(h0) | ((u32)__bfloat16_as_ushort(h1) << 16);
}

__device__ __forceinline__ int edge_at(const void* ei, long long i, int is64) {
    if (is64) return (int)((const long long*)ei)[i];
    return ((const int*)ei)[i];
}

// fp16 row fragment load (4 cols = 8 bytes)
__device__ __forceinline__ float4 ldrow_h(const __half* __restrict__ P, size_t row, int j0) {
    uint2 r = *(const uint2*)(P + row * 128 + j0);
    __half2 h0 = *reinterpret_cast<__half2*>(&r.x);
    __half2 h1 = *reinterpret_cast<__half2*>(&r.y);
    float2 f0 = __half22float2(h0), f1 = __half22float2(h1);
    return make_float4(f0.x, f0.y, f1.x, f1.y);
}

// ---------------- pipelined mainloop: warp tile 32x32, split-bf16 (3 products) ----------------
__device__ __forceinline__ void run_mainloop_p(u32 AHIb, u32 ALOb, u32 BHIb, u32 BLOb,
                                               int m0, int n0, int l, float acc[2][4][4]) {
    int quad = l >> 3;
    int aRow0 = m0 + (l & 7) + ((quad & 1) << 3);
    int aKsel = (quad >> 1) << 4;
    u32 axor = (u32)((aRow0 & 7) << 4);
    u32 arb0 = (u32)(aRow0 * 256);
    u32 arb1 = (u32)((aRow0 + 16) * 256);

    int bRow0 = n0 + (l & 7) + ((quad >> 1) << 3);
    int bKsel = (quad & 1) << 4;
    u32 bxor = (u32)((bRow0 & 7) << 4);
    u32 brb0 = (u32)(bRow0 * 256);
    u32 brb1 = (u32)((bRow0 + 16) * 256);

#pragma unroll
    for (int mf = 0; mf < 2; mf++)
#pragma unroll
        for (int j = 0; j < 4; j++)
#pragma unroll
            for (int k = 0; k < 4; k++) acc[mf][j][k] = 0.f;

    u32 AH0[2][4], AH1[2][4], AL0[2][4], AL1[2][4], BH0[2][4], BH1[2][4];

    {   // prologue: ks = 0 into buffer 0
        u32 kbA = (u32)aKsel ^ axor;
        u32 kbB = (u32)bKsel ^ bxor;
        ldsm4(AHIb + arb0 + kbA, AH0[0]);
        ldsm4(AHIb + arb1 + kbA, AH1[0]);
        ldsm4(ALOb + arb0 + kbA, AL0[0]);
        ldsm4(ALOb + arb1 + kbA, AL1[0]);
        ldsm4(BHIb + brb0 + kbB, BH0[0]);
        ldsm4(BHIb + brb1 + kbB, BH1[0]);
    }

#pragma unroll
    for (int ks = 0; ks < 8; ks++) {
        const int cur = ks & 1, nxt = cur ^ 1;
        u32 kbB = (u32)(ks * 32 + bKsel) ^ bxor;
        u32 bl0[4], bl1[4];
        ldsm4(BLOb + brb0 + kbB, bl0);
        ldsm4(BLOb + brb1 + kbB, bl1);
        if (ks < 7) {
            u32 kbA2 = (u32)((ks + 1) * 32 + aKsel) ^ axor;
            u32 kbB2 = (u32)((ks + 1) * 32 + bKsel) ^ bxor;
            ldsm4(AHIb + arb0 + kbA2, AH0[nxt]);
            ldsm4(AHIb + arb1 + kbA2, AH1[nxt]);
            ldsm4(ALOb + arb0 + kbA2, AL0[nxt]);
            ldsm4(ALOb + arb1 + kbA2, AL1[nxt]);
            ldsm4(BHIb + brb0 + kbB2, BH0[nxt]);
            ldsm4(BHIb + brb1 + kbB2, BH1[nxt]);
        }
#pragma unroll
        for (int j = 0; j < 4; j++) {
            u32 h0 = (j < 2 ? BH0[cur] : BH1[cur])[(j & 1) * 2];
            u32 h1 = (j < 2 ? BH0[cur] : BH1[cur])[(j & 1) * 2 + 1];
            mma_bf16(acc[0][j], AH0[cur], h0, h1);
            mma_bf16(acc[1][j], AH1[cur], h0, h1);
            mma_bf16(acc[0][j], AL0[cur], h0, h1);
            mma_bf16(acc[1][j], AL1[cur], h0, h1);
        }
#pragma unroll
        for (int j = 0; j < 4; j++) {
            u32 l0 = (j < 2 ? bl0 : bl1)[(j & 1) * 2];
            u32 l1 = (j < 2 ? bl0 : bl1)[(j & 1) * 2 + 1];
            mma_bf16(acc[0][j], AH0[cur], l0, l1);
            mma_bf16(acc[1][j], AH1[cur], l0, l1);
        }
    }
}

// fill A planes: 64 rows, 256 threads, fp32 source
__device__ __forceinline__ void fill_A64(char* smem, int OFF_HI, int OFF_LO,
                                         const float* __restrict__ A, int r0, int t) {
#pragma unroll
    for (int i = 0; i < 4; i++) {
        int q = i * 256 + t;
        int r = q >> 4;
        int c = q & 15;
        int gr = r0 + r;
        uint4 hi, lo;
        if (gr < NN) {
            float f[8];
            float4 a0 = *(const float4*)(A + (size_t)gr * 128 + c * 8);
            float4 a1 = *(const float4*)(A + (size_t)gr * 128 + c * 8 + 4);
            f[0] = a0.x; f[1] = a0.y; f[2] = a0.z; f[3] = a0.w;
            f[4] = a1.x; f[5] = a1.y; f[6] = a1.z; f[7] = a1.w;
            split8(f, hi, lo);
        } else {
            hi = make_uint4(0, 0, 0, 0);
            lo = make_uint4(0, 0, 0, 0);
        }
        u32 off = r * 256 + ((c * 16) ^ ((r & 7) << 4));
        *(uint4*)(smem + OFF_HI + off) = hi;
        *(uint4*)(smem + OFF_LO + off) = lo;
    }
}

// fill A planes: 64 rows, 256 threads, fp16 source
__device__ __forceinline__ void fill_A64h(char* smem, int OFF_HI, int OFF_LO,
                                          const __half* __restrict__ A, int r0, int t) {
#pragma unroll
    for (int i = 0; i < 4; i++) {
        int q = i * 256 + t;
        int r = q >> 4;
        int c = q & 15;
        int gr = r0 + r;
        uint4 hi, lo;
        if (gr < NN) {
            uint4 raw = *(const uint4*)(A + (size_t)gr * 128 + c * 8);  // 8 halfs = 16B
            __half2* hp = (__half2*)&raw;
            float f[8];
#pragma unroll
            for (int j = 0; j < 4; j++) {
                float2 fv = __half22float2(hp[j]);
                f[2 * j] = fv.x;
                f[2 * j + 1] = fv.y;
            }
            split8(f, hi, lo);
        } else {
            hi = make_uint4(0, 0, 0, 0);
            lo = make_uint4(0, 0, 0, 0);
        }
        u32 off = r * 256 + ((c * 16) ^ ((r & 7) << 4));
        *(uint4*)(smem + OFF_HI + off) = hi;
        *(uint4*)(smem + OFF_LO + off) = lo;
    }
}

// copy precomputed W planes (64 KB) into smem with 256 threads
__device__ __forceinline__ void copy_B256(char* smem, int OFF_HI, int OFF_LO,
                                          int widx, int t) {
    const uint4* src = (const uint4*)(g_wplanes + widx * 65536);
#pragma unroll
    for (int i = 0; i < 8; i++) {
        int idx = i * 256 + t;
        ((uint4*)(smem + OFF_HI))[idx] = src[idx];
        ((uint4*)(smem + OFF_LO))[idx] = src[2048 + idx];
    }
}

// ---------------- W planes (2 matrices per launch) ----------------
__global__ void wplanes_kernel(const float* __restrict__ Wa, const float* __restrict__ Wb,
                               int base) {
    const float* W = (blockIdx.x == 0) ? Wa : Wb;
    char* dst = g_wplanes + (base + blockIdx.x) * 65536;
    int t = threadIdx.x;
#pragma unroll
    for (int i = 0; i < 8; i++) {
        int q = i * 256 + t;
        int n = q & 127;
        int kb = q >> 7;
        float f[8];
#pragma unroll
        for (int j = 0; j < 8; j++) f[j] = W[(kb * 8 + j) * 128 + n];
        uint4 hi, lo;
        split8(f, hi, lo);
        u32 off = n * 256 + ((kb * 16) ^ ((n & 7) << 4));
        *(uint4*)(dst + off) = hi;
        *(uint4*)(dst + 32768 + off) = lo;
    }
}

// ---------------- dtype detect + degree histogram (4-wide grid-stride) ----------------
// Requires g_deg == 0 on entry (zeroed at load and at END of each run by mlp).
__global__ void degdet_kernel(const void* __restrict__ ei) {
    int b = blockIdx.x, t = threadIdx.x;
    __shared__ int nz;
    if (t == 0) nz = 0;
    __syncthreads();
    const int* ei32 = (const int*)ei;
    int bad = 0;
    for (int j = t; j < 2048; j += 256)
        if (ei32[2 * j + 1] != 0) bad = 1;
    if (bad) atomicOr(&nz, 1);
    __syncthreads();
    int is64 = (nz == 0) ? 1 : 0;
    if (b == 0 && t == 0) g_is64 = is64;

    const long long S = (long long)NB_SCAN * 256;
    long long e = (long long)b * 256 + t;
    for (; e + 3 * S < EE; e += 4 * S) {
        int d0 = edge_at(ei, EE + e, is64);
        int d1 = edge_at(ei, EE + e + S, is64);
        int d2 = edge_at(ei, EE + e + 2 * S, is64);
        int d3 = edge_at(ei, EE + e + 3 * S, is64);
        atomicAdd(&g_deg[d0], 1);
        atomicAdd(&g_deg[d1], 1);
        atomicAdd(&g_deg[d2], 1);
        atomicAdd(&g_deg[d3], 1);
    }
    for (; e < EE; e += S) {
        int d = edge_at(ei, EE + e, is64);
        atomicAdd(&g_deg[d], 1);
    }
}

// ---------------- scans ----------------
__global__ void scan1_kernel() {
    __shared__ int sm[256];
    int i = blockIdx.x * 256 + threadIdx.x;
    int v = (i < NN) ? g_deg[i] : 0;
    sm[threadIdx.x] = v;
    __syncthreads();
    for (int s = 1; s < 256; s <<= 1) {
        int add = (threadIdx.x >= (unsigned)s) ? sm[threadIdx.x - s] : 0;
        __syncthreads();
        sm[threadIdx.x] += add;
        __syncthreads();
    }
    if (i < NN) g_off[i] = sm[threadIdx.x];
    if (threadIdx.x == 255) g_bsum[blockIdx.x] = sm[255];
}

__global__ void scan2b_kernel() {
    __shared__ int sm[512];
    int t = threadIdx.x;
    sm[t] = (t < NB_SCAN) ? g_bsum[t] : 0;
    __syncthreads();
    for (int s = 1; s < 512; s <<= 1) {
        int add = (t >= s) ? sm[t - s] : 0;
        __syncthreads();
        sm[t] += add;
        __syncthreads();
    }
    if (t < 256) {
        int i = blockIdx.x * 256 + t;
        if (i < NN) {
            int base = (blockIdx.x > 0) ? sm[blockIdx.x - 1] : 0;
            int d = g_deg[i];
            int excl = base + g_off[i] - d;
            g_off[i] = excl;
            g_cur[i] = excl;
            g_dinv[i] = rsqrtf((float)(d + 1));
        }
    }
}

// ---------------- CSR fill (4 edges per thread — proven best) ----------------
__global__ void fill_kernel(const void* __restrict__ ei) {
    int base = (blockIdx.x * blockDim.x + threadIdx.x) * 4;
    int is64 = g_is64;
    int s[4], d[4];
#pragma unroll
    for (int u = 0; u < 4; u++) {
        if (base + u < EE) {
            s[u] = edge_at(ei, base + u, is64);
            d[u] = edge_at(ei, (long long)EE + base + u, is64);
        } else {
            s[u] = -1;
        }
    }
#pragma unroll
    for (int u = 0; u < 4; u++) {
        if (s[u] >= 0) {
            int pos = atomicAdd(&g_cur[d[u]], 1);
            g_csr[pos] = s[u];
        }
    }
}

// ---------------- aggregation: gather fp16 P -> fp32 accum -> fp16 out ----------------
// PREMUL=1: P rows already scaled by dinv[src] at GEMM epilogue (no dinv gathers).
template <int PREMUL>
__global__ void agg_kernel(const __half* __restrict__ P, __half* __restrict__ O,
                           const float* __restrict__ bias,
                           const float* __restrict__ g, const float* __restrict__ be,
                           const float* __restrict__ m, const float* __restrict__ v) {
    int node = (blockIdx.x * blockDim.x + threadIdx.x) >> 5;
    int lane = threadIdx.x & 31;
    if (node >= NN) return;
    float dn = g_dinv[node];
    int j0 = lane * 4;

    float4 self = ldrow_h(P, (size_t)node, j0);
    float4 acc;
    if (PREMUL) {
        acc = self;                      // Ppre[node] = dinv[node]*P[node]
    } else {
        acc.x = self.x * dn;
        acc.y = self.y * dn;
        acc.z = self.z * dn;
        acc.w = self.w * dn;
    }

    int st = g_off[node];
    int en = st + g_deg[node];
    int e = st;
    for (; e + 8 <= en; e += 8) {
        int s0 = g_csr[e],     s1 = g_csr[e + 1], s2 = g_csr[e + 2], s3 = g_csr[e + 3];
        int s4 = g_csr[e + 4], s5 = g_csr[e + 5], s6 = g_csr[e + 6], s7 = g_csr[e + 7];
        float w0 = 1.f, w1 = 1.f, w2 = 1.f, w3 = 1.f, w4 = 1.f, w5 = 1.f, w6 = 1.f, w7 = 1.f;
        if (!PREMUL) {
            w0 = g_dinv[s0]; w1 = g_dinv[s1]; w2 = g_dinv[s2]; w3 = g_dinv[s3];
            w4 = g_dinv[s4]; w5 = g_dinv[s5]; w6 = g_dinv[s6]; w7 = g_dinv[s7];
        }
        float4 p0 = ldrow_h(P, (size_t)s0, j0);
        float4 p1 = ldrow_h(P, (size_t)s1, j0);
        float4 p2 = ldrow_h(P, (size_t)s2, j0);
        float4 p3 = ldrow_h(P, (size_t)s3, j0);
        float4 p4 = ldrow_h(P, (size_t)s4, j0);
        float4 p5 = ldrow_h(P, (size_t)s5, j0);
        float4 p6 = ldrow_h(P, (size_t)s6, j0);
        float4 p7 = ldrow_h(P, (size_t)s7, j0);
        if (PREMUL) {
            acc.x += p0.x + p1.x + p2.x + p3.x + p4.x + p5.x + p6.x + p7.x;
            acc.y += p0.y + p1.y + p2.y + p3.y + p4.y + p5.y + p6.y + p7.y;
            acc.z += p0.z + p1.z + p2.z + p3.z + p4.z + p5.z + p6.z + p7.z;
            acc.w += p0.w + p1.w + p2.w + p3.w + p4.w + p5.w + p6.w + p7.w;
        } else {
            acc.x += p0.x * w0 + p1.x * w1 + p2.x * w2 + p3.x * w3 +
                     p4.x * w4 + p5.x * w5 + p6.x * w6 + p7.x * w7;
            acc.y += p0.y * w0 + p1.y * w1 + p2.y * w2 + p3.y * w3 +
                     p4.y * w4 + p5.y * w5 + p6.y * w6 + p7.y * w7;
            acc.z += p0.z * w0 + p1.z * w1 + p2.z * w2 + p3.z * w3 +
                     p4.z * w4 + p5.z * w5 + p6.z * w6 + p7.z * w7;
            acc.w += p0.w * w0 + p1.w * w1 + p2.w * w2 + p3.w * w3 +
                     p4.w * w4 + p5.w * w5 + p6.w * w6 + p7.w * w7;
        }
    }
    for (; e < en; e++) {
        int s = g_csr[e];
        float w = PREMUL ? 1.f : g_dinv[s];
        float4 p = ldrow_h(P, (size_t)s, j0);
        acc.x += p.x * w;
        acc.y += p.y * w;
        acc.z += p.z * w;
        acc.w += p.w * w;
    }

    float4 b4  = *(const float4*)(bias + j0);
    float4 g4  = *(const float4*)(g + j0);
    float4 be4 = *(const float4*)(be + j0);
    float4 m4  = *(const float4*)(m + j0);
    float4 v4  = *(const float4*)(v + j0);

    float4 o;
    { float x = acc.x * dn + b4.x; float s = g4.x * rsqrtf(v4.x + BN_EPS); o.x = fmaxf((x - m4.x) * s + be4.x, 0.f); }
    { float x = acc.y * dn + b4.y; float s = g4.y * rsqrtf(v4.y + BN_EPS); o.y = fmaxf((x - m4.y) * s + be4.y, 0.f); }
    { float x = acc.z * dn + b4.z; float s = g4.z * rsqrtf(v4.z + BN_EPS); o.z = fmaxf((x - m4.z) * s + be4.z, 0.f); }
    { float x = acc.w * dn + b4.w; float s = g4.w * rsqrtf(v4.w + BN_EPS); o.w = fmaxf((x - m4.w) * s + be4.w, 0.f); }

    __half2 h01 = __floats2half2_rn(o.x, o.y);
    __half2 h23 = __floats2half2_rn(o.z, o.w);
    uint2 st2;
    st2.x = *(u32*)&h01;
    st2.y = *(u32*)&h23;
    *(uint2*)(O + (size_t)node * 128 + j0) = st2;
}

// ---------------- plain GEMM: 64x128 tile, 2 CTAs/SM, fp16 out ----------------
// HIN: input dtype (0=fp32, 1=fp16). PREMUL: scale output rows by g_dinv[row].
#define G_AHI 0
#define G_ALO 16384
#define G_BHI 32768
#define G_BLO 65536
#define G_SMEM 98304

template <int HIN, int PREMUL>
__global__ void __launch_bounds__(256, 2)
gemm_plain_kernel(const void* __restrict__ A, int widx, __half* __restrict__ C) {
    extern __shared__ char smem[];
    u32 sb = smem_u32(smem);
    int t = threadIdx.x;
    int wid = t >> 5;
    int l = t & 31;
    int r0 = blockIdx.x * 64;

    if (HIN) fill_A64h(smem, G_AHI, G_ALO, (const __half*)A, r0, t);
    else     fill_A64(smem, G_AHI, G_ALO, (const float*)A, r0, t);
    copy_B256(smem, G_BHI, G_BLO, widx, t);
    __syncthreads();

    int m0 = (wid & 1) * 32;
    int n0 = (wid >> 1) * 32;
    float acc[2][4][4];
    run_mainloop_p(sb + G_AHI, sb + G_ALO, sb + G_BHI, sb + G_BLO, m0, n0, l, acc);

    int crow = l >> 2;
    int ccol = (l & 3) * 2;
#pragma unroll
    for (int mf = 0; mf < 2; mf++) {
        int rowA = m0 + mf * 16 + crow;
        float dA = 1.f, dB = 1.f;
        if (PREMUL) {
            int grA = r0 + rowA;
            if (grA < NN) dA = g_dinv[grA];
            if (grA + 8 < NN) dB = g_dinv[grA + 8];
        }
#pragma unroll
        for (int j = 0; j < 4; j++) {
            int col = n0 + j * 8 + ccol;
            int gr = r0 + rowA;
            if (gr < NN)
                *(__half2*)(C + (size_t)gr * 128 + col) =
                    __floats2half2_rn(acc[mf][j][0] * dA, acc[mf][j][1] * dA);
            if (gr + 8 < NN)
                *(__half2*)(C + (size_t)(gr + 8) * 128 + col) =
                    __floats2half2_rn(acc[mf][j][2] * dB, acc[mf][j][3] * dB);
        }
    }
}

// ---------------- fused MLP: fp16 H input, B-plane swap; resets g_deg at end ----------------
#define M_SC3  0
#define M_SH3  512
#define M_BF2  1024
#define M_WO   1536
#define M_AHI  2048
#define M_ALO  18432
#define M_BHI  34816
#define M_BLO  67584
#define M_C    34816
#define M_SMEM 100352

__global__ void __launch_bounds__(256, 2)
mlp_fused_kernel(const __half* __restrict__ H,
                 const float* __restrict__ bf1,
                 const float* __restrict__ g3, const float* __restrict__ be3,
                 const float* __restrict__ m3, const float* __restrict__ v3,
                 const float* __restrict__ bf2,
                 const float* __restrict__ Wo, const float* __restrict__ bo,
                 float* __restrict__ h1_out, float* __restrict__ pred) {
    extern __shared__ char smem[];
    u32 sb = smem_u32(smem);
    float* smf = (float*)smem;
    int t = threadIdx.x;
    int wid = t >> 5;
    int l = t & 31;
    int r0 = blockIdx.x * 64;

    // reset g_deg for the next run (agg2 already consumed it)
    {
        int i = blockIdx.x * 256 + t;
        if (i < NN) g_deg[i] = 0;
    }

    if (t < 128) {
        float s = g3[t] * rsqrtf(v3[t] + BN_EPS);
        smf[M_SC3 / 4 + t] = s;
        smf[M_SH3 / 4 + t] = (bf1[t] - m3[t]) * s + be3[t];
        smf[M_BF2 / 4 + t] = bf2[t];
        smf[M_WO / 4 + t]  = Wo[t];
    }
    copy_B256(smem, M_BHI, M_BLO, 2, t);   // Wf1
    fill_A64h(smem, M_AHI, M_ALO, H, r0, t);
    __syncthreads();

    int m0 = (wid & 1) * 32;
    int n0 = (wid >> 1) * 32;
    int crow = l >> 2;
    int ccol = (l & 3) * 2;

    float acc[2][4][4];
    run_mainloop_p(sb + M_AHI, sb + M_ALO, sb + M_BHI, sb + M_BLO, m0, n0, l, acc);
    __syncthreads();   // all warps done reading A + B1 planes

    // X3 = relu(acc*sc3 + sh3) -> rewrite A planes; swap in Wf2 planes
#pragma unroll
    for (int mf = 0; mf < 2; mf++) {
#pragma unroll
        for (int j = 0; j < 4; j++) {
            int row = m0 + mf * 16 + crow;
            int col = n0 + j * 8 + ccol;
            float sc0 = smf[M_SC3 / 4 + col],     sh0 = smf[M_SH3 / 4 + col];
            float sc1 = smf[M_SC3 / 4 + col + 1], sh1 = smf[M_SH3 / 4 + col + 1];
            float x0 = fmaxf(acc[mf][j][0] * sc0 + sh0, 0.f);
            float x1 = fmaxf(acc[mf][j][1] * sc1 + sh1, 0.f);
            float x2 = fmaxf(acc[mf][j][2] * sc0 + sh0, 0.f);
            float x3 = fmaxf(acc[mf][j][3] * sc1 + sh1, 0.f);
            u32 lo0, lo1;
            u32 hi0 = pack_hilo2(x0, x1, lo0);
            u32 hi1 = pack_hilo2(x2, x3, lo1);
            u32 cb = (u32)(col * 2);
            u32 off0 = (u32)(row * 256) + ((cb & ~15u) ^ ((u32)(row & 7) << 4)) + (cb & 15u);
            int row2 = row + 8;
            u32 off1 = (u32)(row2 * 256) + ((cb & ~15u) ^ ((u32)(row2 & 7) << 4)) + (cb & 15u);
            *(u32*)(smem + M_AHI + off0) = hi0;
            *(u32*)(smem + M_ALO + off0) = lo0;
            *(u32*)(smem + M_AHI + off1) = hi1;
            *(u32*)(smem + M_ALO + off1) = lo1;
        }
    }
    copy_B256(smem, M_BHI, M_BLO, 3, t);   // Wf2 over Wf1
    __syncthreads();

    run_mainloop_p(sb + M_AHI, sb + M_ALO, sb + M_BHI, sb + M_BLO, m0, n0, l, acc);
    __syncthreads();   // B planes reused as C staging

    // h1 = relu(acc + bf2), stage to C (512B rows, 16B-block swizzle)
#pragma unroll
    for (int mf = 0; mf < 2; mf++) {
#pragma unroll
        for (int j = 0; j < 4; j++) {
            int row = m0 + mf * 16 + crow;
            int col = n0 + j * 8 + ccol;
            float b0 = smf[M_BF2 / 4 + col], b1 = smf[M_BF2 / 4 + col + 1];
            float v0 = fmaxf(acc[mf][j][0] + b0, 0.f);
            float v1 = fmaxf(acc[mf][j][1] + b1, 0.f);
            float v2 = fmaxf(acc[mf][j][2] + b0, 0.f);
            float v3v = fmaxf(acc[mf][j][3] + b1, 0.f);
            u32 o1 = (u32)(row * 512) + (((u32)(col * 4)) ^ ((u32)(row & 7) << 4));
            *(float2*)(smem + M_C + o1) = make_float2(v0, v1);
            int row2 = row + 8;
            u32 o2 = (u32)(row2 * 512) + (((u32)(col * 4)) ^ ((u32)(row2 & 7) << 4));
            *(float2*)(smem + M_C + o2) = make_float2(v2, v3v);
        }
    }
    __syncthreads();

    // pred = softplus(h1 . Wo + bo)
    if (t < 64) {
        int gr = r0 + t;
        if (gr < NN) {
            float dot = bo[0];
#pragma unroll 8
            for (int c16 = 0; c16 < 32; c16++) {
                u32 off = (u32)(t * 512) + (((u32)(c16 * 16)) ^ ((u32)(t & 7) << 4));
                float4 hv = *(float4*)(smem + M_C + off);
                int col = c16 * 4;
                dot += hv.x * smf[M_WO / 4 + col] + hv.y * smf[M_WO / 4 + col + 1] +
                       hv.z * smf[M_WO / 4 + col + 2] + hv.w * smf[M_WO / 4 + col + 3];
            }
            pred[gr] = fmaxf(dot, 0.f) + log1pf(expf(-fabsf(dot)));  // logaddexp(dot,0)
        }
    }

    // coalesced h1 copy-out (fp32 — it is part of the output)
#pragma unroll
    for (int i = 0; i < 8; i++) {
        int lin = i * 256 + t;
        int row = lin >> 5;
        int c16 = lin & 31;
        int gr = r0 + row;
        if (gr >= NN) continue;
        u32 off = (u32)(row * 512) + (((u32)(c16 * 16)) ^ ((u32)(row & 7) << 4));
        float4 val = *(float4*)(smem + M_C + off);
        *(float4*)(h1_out + (size_t)gr * 128 + c16 * 4) = val;
    }
}

// ---------------- launcher ----------------
extern "C" void kernel_launch(void* const* d_in, const int* in_sizes, int n_in,
                              void* d_out, int out_size) {
    const float* x   = (const float*)d_in[0];
    const void*  ei  = d_in[1];
    const float* W1  = (const float*)d_in[2];
    const float* b1  = (const float*)d_in[3];
    const float* W2  = (const float*)d_in[4];
    const float* b2  = (const float*)d_in[5];
    const float* Wf1 = (const float*)d_in[6];
    const float* bf1 = (const float*)d_in[7];
    const float* Wf2 = (const float*)d_in[8];
    const float* bf2 = (const float*)d_in[9];
    const float* Wo  = (const float*)d_in[10];
    const float* bo  = (const float*)d_in[11];
    const float* g1  = (const float*)d_in[12];
    const float* be1 = (const float*)d_in[13];
    const float* m1  = (const float*)d_in[14];
    const float* v1  = (const float*)d_in[15];
    const float* g2  = (const float*)d_in[16];
    const float* be2 = (const float*)d_in[17];
    const float* m2  = (const float*)d_in[18];
    const float* v2  = (const float*)d_in[19];
    const float* g3  = (const float*)d_in[20];
    const float* be3 = (const float*)d_in[21];
    const float* m3  = (const float*)d_in[22];
    const float* v3  = (const float*)d_in[23];

    float* out = (float*)d_out;
    float* h1_out = out + NN;    // output layout: (raw_pred[N], h1[N,128])

    float *bufA = nullptr, *bufB = nullptr;
    cudaGetSymbolAddress((void**)&bufA, g_bufA);
    cudaGetSymbolAddress((void**)&bufB, g_bufB);
    __half* P = (__half*)bufA;   // fp16 projections
    __half* Hh = (__half*)bufB;  // fp16 hidden

    cudaFuncSetAttribute((const void*)gemm_plain_kernel<0, 0>,
                         cudaFuncAttributeMaxDynamicSharedMemorySize, G_SMEM);
    cudaFuncSetAttribute((const void*)gemm_plain_kernel<1, 1>,
                         cudaFuncAttributeMaxDynamicSharedMemorySize, G_SMEM);
    cudaFuncSetAttribute((const void*)mlp_fused_kernel,
                         cudaFuncAttributeMaxDynamicSharedMemorySize, M_SMEM);

    // lazily created host-side resources (no device memory involved);
    // fall back to single-stream if creation fails for any reason
    static cudaStream_t s2 = nullptr;
    static cudaEvent_t evFork = nullptr, evJoin = nullptr;
    static int ok = -1;
    if (ok < 0) {
        ok = 1;
        if (cudaStreamCreateWithFlags(&s2, cudaStreamNonBlocking) != cudaSuccess) ok = 0;
        if (ok && cudaEventCreateWithFlags(&evFork, cudaEventDisableTiming) != cudaSuccess) ok = 0;
        if (ok && cudaEventCreateWithFlags(&evJoin, cudaEventDisableTiming) != cudaSuccess) ok = 0;
    }

    const int NB = NB_SCAN;                    // 391
    const int EB4 = (EE + 1023) / 1024;        // 4 edges/thread
    const int GB = (NN + 63) / 64;             // 1563
    const int AB = (NN + 7) / 8;               // warp per node

    cudaStream_t sW = ok ? s2 : (cudaStream_t)0;

    // submission order (0-based; index 3 profiled): wplanesA(0 sW), wplanesB(1 sW),
    // gemm1(2 sW), degdet(3 s0) <- ncu, scan1(4), scan2b(5), fill(6), join, tail.
    if (ok) {
        cudaEventRecord(evFork, 0);
        cudaStreamWaitEvent(s2, evFork, 0);
    }

    wplanes_kernel<<<2, 256, 0, sW>>>(W1, W2, 0);                   // 0 (sW)
    wplanes_kernel<<<2, 256, 0, sW>>>(Wf1, Wf2, 2);                 // 1 (sW)
    gemm_plain_kernel<0, 0><<<GB, 256, G_SMEM, sW>>>(x, 0, P);      // 2 (sW)
    degdet_kernel<<<NB, 256>>>(ei);                                 // 3 (s0) <- ncu
    scan1_kernel<<<NB, 256>>>();                                    // 4 (s0)
    scan2b_kernel<<<NB, 512>>>();                                   // 5 (s0)
    fill_kernel<<<EB4, 256>>>(ei);                                  // 6 (s0)

    if (ok) {
        cudaEventRecord(evJoin, s2);
        cudaStreamWaitEvent(0, evJoin, 0);
    }
    agg_kernel<0><<<AB, 256>>>(P, Hh, b1, g1, be1, m1, v1);         // 7
    gemm_plain_kernel<1, 1><<<GB, 256, G_SMEM>>>(Hh, 1, P);         // 8 (premul dinv)
    agg_kernel<1><<<AB, 256>>>(P, Hh, b2, g2, be2, m2, v2);         // 9
    mlp_fused_kernel<<<GB, 256, M_SMEM>>>(Hh, bf1, g3, be3, m3, v3,
                                          bf2, Wo, bo, h1_out, out); // 10
}